// round 1
// baseline (speedup 1.0000x reference)
#include <cuda_runtime.h>
#include <math_constants.h>

// Problem constants (fixed by reference)
namespace {
constexpr int B_  = 64;
constexpr int T_  = 256;
constexpr int DM  = 512;   // d_model
constexpr int H_  = 8;     // heads
constexpr int DK  = 64;    // head dim
constexpr int NTOK = B_ * T_;  // 16384
}

// Scratch (device globals — no allocation allowed in kernel_launch)
__device__ float g_Q[B_ * H_ * T_ * DK];     // 32 MB
__device__ float g_K[B_ * H_ * T_ * DK];     // 32 MB
__device__ float g_V[B_ * H_ * T_ * DK];     // 32 MB
__device__ float g_att[NTOK * DM];           // 32 MB (concat attention output)

// ---------------------------------------------------------------------------
// Kernel 1: QKV projection.
// Q[b,h,t,d] = sum_c x[b,t,c] * Wq[h,c,d]   (same for K, V)
// Tiled SGEMM: M-tile 64 (tokens), N = 64 (= DK, one head), K = 512, BK = 16.
// grid = (NTOK/64, 3*H).  gridDim.y encodes (which matrix, head).
// ---------------------------------------------------------------------------
__global__ __launch_bounds__(256) void qkv_kernel(
    const float* __restrict__ x,
    const float* __restrict__ Wq,
    const float* __restrict__ Wk,
    const float* __restrict__ Wv)
{
    __shared__ float As[16][64];   // [k][m]
    __shared__ float Bs[16][64];   // [k][n]

    const int tid = threadIdx.x;
    const int tx = tid & 15;       // 0..15 -> n
    const int ty = tid >> 4;       // 0..15 -> m

    const int mtile = blockIdx.x * 64;
    const int y     = blockIdx.y;        // 0..23
    const int h     = y & 7;
    const int which = y >> 3;            // 0=Q 1=K 2=V

    const float* W = (which == 0) ? Wq : (which == 1) ? Wk : Wv;
    W += (size_t)h * DM * DK;
    float* outp = (which == 0) ? g_Q : (which == 1) ? g_K : g_V;

    // load indices
    const int a_row = tid >> 2;          // 0..63
    const int a_kq  = (tid & 3) * 4;     // 0,4,8,12
    const int b_row = tid >> 4;          // 0..15 (k)
    const int b_dq  = (tid & 15) * 4;    // 0..60 (n)

    float acc[4][4] = {};

    for (int k0 = 0; k0 < DM; k0 += 16) {
        // As: x[(mtile+a_row)][k0+a_kq .. +3]
        float4 av = *(const float4*)(x + (size_t)(mtile + a_row) * DM + k0 + a_kq);
        As[a_kq + 0][a_row] = av.x;
        As[a_kq + 1][a_row] = av.y;
        As[a_kq + 2][a_row] = av.z;
        As[a_kq + 3][a_row] = av.w;
        // Bs: W[(k0+b_row)][b_dq .. +3]
        float4 bv = *(const float4*)(W + (size_t)(k0 + b_row) * DK + b_dq);
        *(float4*)&Bs[b_row][b_dq] = bv;
        __syncthreads();

        #pragma unroll
        for (int kk = 0; kk < 16; ++kk) {
            float4 a = *(const float4*)&As[kk][ty * 4];
            float4 b = *(const float4*)&Bs[kk][tx * 4];
            float ar[4] = {a.x, a.y, a.z, a.w};
            float br[4] = {b.x, b.y, b.z, b.w};
            #pragma unroll
            for (int i = 0; i < 4; ++i)
                #pragma unroll
                for (int j = 0; j < 4; ++j)
                    acc[i][j] = fmaf(ar[i], br[j], acc[i][j]);
        }
        __syncthreads();
    }

    // Write: out[((b*H+h)*T + t)*DK + d], token m = mtile + ty*4 + i
    #pragma unroll
    for (int i = 0; i < 4; ++i) {
        const int m = mtile + ty * 4 + i;
        const int b = m >> 8;       // m / T
        const int t = m & 255;      // m % T
        float* dst = outp + ((size_t)(b * H_ + h) * T_ + t) * DK + tx * 4;
        float4 v = make_float4(acc[i][0], acc[i][1], acc[i][2], acc[i][3]);
        *(float4*)dst = v;
    }
}

// ---------------------------------------------------------------------------
// Kernel 2: causal attention per (b,h).
// One CTA per (b,h): K,V (256x64 fp32 each) resident in 128 KB dynamic SMEM.
// One thread per query row t; online softmax over s=0..t.
// Writes directly into concat layout g_att[(b*T+t)*DM + h*DK + d].
// ---------------------------------------------------------------------------
__global__ __launch_bounds__(256) void attn_kernel()
{
    extern __shared__ float sm[];
    float* Ks = sm;                 // [T_][DK]
    float* Vs = sm + T_ * DK;       // [T_][DK]

    const int bid = blockIdx.x;     // 0..511
    const int b = bid >> 3;
    const int h = bid & 7;
    const size_t base = (size_t)(b * H_ + h) * T_ * DK;
    const int tid = threadIdx.x;    // = query row t

    // cooperative K,V load (float4)
    const float4* gk = (const float4*)(g_K + base);
    const float4* gv = (const float4*)(g_V + base);
    #pragma unroll
    for (int i = tid; i < T_ * DK / 4; i += 256) {
        ((float4*)Ks)[i] = gk[i];
        ((float4*)Vs)[i] = gv[i];
    }

    // this thread's query row into registers
    float q[DK];
    {
        const float4* gq = (const float4*)(g_Q + base + (size_t)tid * DK);
        #pragma unroll
        for (int i = 0; i < DK / 4; ++i) {
            float4 v = gq[i];
            q[i * 4 + 0] = v.x; q[i * 4 + 1] = v.y;
            q[i * 4 + 2] = v.z; q[i * 4 + 3] = v.w;
        }
    }
    __syncthreads();

    const float scale = 0.04419417382415922f;   // 1/sqrt(512)

    float m = -CUDART_INF_F;
    float l = 0.0f;
    float o[DK];
    #pragma unroll
    for (int d = 0; d < DK; ++d) o[d] = 0.0f;

    for (int s = 0; s <= tid; ++s) {
        const float* kr = Ks + s * DK;
        float dot = 0.0f;
        #pragma unroll
        for (int d = 0; d < DK; ++d) dot = fmaf(q[d], kr[d], dot);
        const float xv = dot * scale;

        const float nm   = fmaxf(m, xv);
        const float corr = __expf(m - nm);    // 0 on first iter (m = -inf)
        const float p    = __expf(xv - nm);
        l = l * corr + p;
        const float* vr = Vs + s * DK;
        #pragma unroll
        for (int d = 0; d < DK; ++d)
            o[d] = fmaf(o[d], corr, p * vr[d]);
        m = nm;
    }

    const float inv = 1.0f / l;
    float* op = g_att + (size_t)(b * T_ + tid) * DM + h * DK;
    #pragma unroll
    for (int d = 0; d < DK; d += 4) {
        float4 v = make_float4(o[d] * inv, o[d + 1] * inv, o[d + 2] * inv, o[d + 3] * inv);
        *(float4*)(op + d) = v;
    }
}

// ---------------------------------------------------------------------------
// Kernel 3: output projection.  out = g_att (16384x512) @ Wo (512x512)
// Same 64x64 tiled SGEMM, grid = (NTOK/64, DM/64).
// ---------------------------------------------------------------------------
__global__ __launch_bounds__(256) void oproj_kernel(
    const float* __restrict__ Wo,
    float* __restrict__ out)
{
    __shared__ float As[16][64];   // [k][m]
    __shared__ float Bs[16][64];   // [k][n]

    const int tid = threadIdx.x;
    const int tx = tid & 15;
    const int ty = tid >> 4;

    const int mtile = blockIdx.x * 64;
    const int ntile = blockIdx.y * 64;

    const int a_row = tid >> 2;
    const int a_kq  = (tid & 3) * 4;
    const int b_row = tid >> 4;
    const int b_dq  = (tid & 15) * 4;

    float acc[4][4] = {};

    for (int k0 = 0; k0 < DM; k0 += 16) {
        float4 av = *(const float4*)(g_att + (size_t)(mtile + a_row) * DM + k0 + a_kq);
        As[a_kq + 0][a_row] = av.x;
        As[a_kq + 1][a_row] = av.y;
        As[a_kq + 2][a_row] = av.z;
        As[a_kq + 3][a_row] = av.w;
        float4 bv = *(const float4*)(Wo + (size_t)(k0 + b_row) * DM + ntile + b_dq);
        *(float4*)&Bs[b_row][b_dq] = bv;
        __syncthreads();

        #pragma unroll
        for (int kk = 0; kk < 16; ++kk) {
            float4 a = *(const float4*)&As[kk][ty * 4];
            float4 b = *(const float4*)&Bs[kk][tx * 4];
            float ar[4] = {a.x, a.y, a.z, a.w};
            float br[4] = {b.x, b.y, b.z, b.w};
            #pragma unroll
            for (int i = 0; i < 4; ++i)
                #pragma unroll
                for (int j = 0; j < 4; ++j)
                    acc[i][j] = fmaf(ar[i], br[j], acc[i][j]);
        }
        __syncthreads();
    }

    #pragma unroll
    for (int i = 0; i < 4; ++i) {
        float* dst = out + (size_t)(mtile + ty * 4 + i) * DM + ntile + tx * 4;
        float4 v = make_float4(acc[i][0], acc[i][1], acc[i][2], acc[i][3]);
        *(float4*)dst = v;
    }
}

// ---------------------------------------------------------------------------
extern "C" void kernel_launch(void* const* d_in, const int* in_sizes, int n_in,
                              void* d_out, int out_size)
{
    const float* x  = (const float*)d_in[0];
    const float* Wq = (const float*)d_in[1];
    const float* Wk = (const float*)d_in[2];
    const float* Wv = (const float*)d_in[3];
    const float* Wo = (const float*)d_in[4];
    float* out = (float*)d_out;

    // 1. QKV projections
    qkv_kernel<<<dim3(NTOK / 64, 3 * H_), 256>>>(x, Wq, Wk, Wv);

    // 2. attention (128 KB dynamic smem for K,V tiles)
    const int smem_bytes = 2 * T_ * DK * (int)sizeof(float);   // 131072
    cudaFuncSetAttribute(attn_kernel, cudaFuncAttributeMaxDynamicSharedMemorySize,
                         smem_bytes);
    attn_kernel<<<B_ * H_, 256, smem_bytes>>>();

    // 3. output projection
    oproj_kernel<<<dim3(NTOK / 64, DM / 64), 256>>>(Wo, out);
}

// round 3
// speedup vs baseline: 1.8268x; 1.8268x over previous
#include <cuda_runtime.h>
#include <math_constants.h>
#include <cstdint>

// ---------------------------------------------------------------------------
// Problem constants
// ---------------------------------------------------------------------------
namespace {
constexpr int B_  = 64;
constexpr int T_  = 256;
constexpr int DM  = 512;   // d_model
constexpr int H_  = 8;     // heads
constexpr int DK  = 64;    // head dim
constexpr int NTOK = B_ * T_;  // 16384
}

// Scratch (device globals — no allocation allowed in kernel_launch)
__device__ float g_Q[B_ * H_ * T_ * DK];
__device__ float g_K[B_ * H_ * T_ * DK];
__device__ float g_V[B_ * H_ * T_ * DK];
__device__ float g_att[NTOK * DM];

// ---------------------------------------------------------------------------
// Helpers
// ---------------------------------------------------------------------------
__device__ __forceinline__ uint32_t f2tf32(float f) {
    uint32_t r;
    asm("cvt.rna.tf32.f32 %0, %1;" : "=r"(r) : "f"(f));
    return r;
}

__device__ __forceinline__ void mma_tf32(float& d0, float& d1, float& d2, float& d3,
                                         uint32_t a0, uint32_t a1, uint32_t a2, uint32_t a3,
                                         uint32_t b0, uint32_t b1) {
    asm volatile(
        "mma.sync.aligned.m16n8k8.row.col.f32.tf32.tf32.f32 "
        "{%0,%1,%2,%3}, {%4,%5,%6,%7}, {%8,%9}, {%0,%1,%2,%3};"
        : "+f"(d0), "+f"(d1), "+f"(d2), "+f"(d3)
        : "r"(a0), "r"(a1), "r"(a2), "r"(a3), "r"(b0), "r"(b1));
}

// ---------------------------------------------------------------------------
// tf32 mma.sync GEMM. CTA tile 128(M) x 128(N), BK=16, 8 warps (4m x 2n),
// warp tile 32x64. Register prefetch of next K-slab overlaps compute.
//
// MODE 0: qkv — A = x [16384,512]; columns (which,head,d) drawn from Wq/Wk/Wv
//         (logical B is [1536, 512] n-major); output scattered to g_Q/g_K/g_V.
// MODE 1: oproj — A = g_att [16384,512]; B = Wo [512,512]; output = d_out.
// ---------------------------------------------------------------------------
namespace {
constexpr int BM = 128, BN = 128, BK = 16;
constexpr int KITERS = DM / BK;   // 32
constexpr int APAD = 4;
}

template <int MODE>
__global__ __launch_bounds__(256, 2) void gemm_mma(
    const float* __restrict__ Ain,
    const float* __restrict__ Wq,
    const float* __restrict__ Wk,
    const float* __restrict__ Wv,
    float* __restrict__ outp)
{
    __shared__ uint32_t As[BK][BM + APAD];   // [k][m] tf32 bits
    __shared__ uint32_t Bs[BK][BN + APAD];   // [k][n] tf32 bits

    const int tid  = threadIdx.x;
    const int wid  = tid >> 5;
    const int lane = tid & 31;
    const int g    = lane >> 2;   // group id 0..7
    const int tg   = lane & 3;    // thread-in-group 0..3

    const int warp_m = wid & 3;   // 0..3 -> 32-row slice
    const int warp_n = wid >> 2;  // 0..1 -> 64-col slice

    const int mtile = blockIdx.x * BM;
    const int ntile = blockIdx.y * BN;

    const float* A = (MODE == 0) ? Ain : (const float*)g_att;
    const float* Bsrc;
    int which = 0, nbase = 0;
    if (MODE == 0) {
        which = ntile >> 9;           // 0=Q 1=K 2=V
        nbase = ntile & 511;          // col offset within the 512-wide group
        Bsrc = (which == 0) ? Wq : (which == 1) ? Wk : Wv;
    } else {
        Bsrc = Wq;   // Wo passed in slot 0
    }

    // ---- global-load index precompute (2 float4 each for A and B) ----
    // A: elem-quad i in [0,512): row=i/4, col4=i%4. thread does i=tid, tid+256.
    const int ar0 = tid >> 2,        ac0 = (tid & 3) * 4;
    const int ar1 = (tid + 256) >> 2, ac1 = ((tid + 256) & 3) * 4;
    // B: quad f in [0,512): k=f/32, n=4*(f%32). thread does f=tid, tid+256.
    const int bk0 = tid >> 5,        bn0 = (tid & 31) * 4;
    const int bk1 = (tid + 256) >> 5, bn1 = ((tid + 256) & 31) * 4;

    auto loadB = [&](int k0, int k, int n) -> float4 {
        if (MODE == 0) {
            const int nloc = nbase + n;
            const int h = nloc >> 6, dd = nloc & 63;
            return *(const float4*)(Bsrc + ((size_t)h * DM + k0 + k) * DK + dd);
        } else {
            return *(const float4*)(Bsrc + (size_t)(k0 + k) * DM + ntile + n);
        }
    };

    float acc[2][8][4];
    #pragma unroll
    for (int i = 0; i < 2; ++i)
        #pragma unroll
        for (int j = 0; j < 8; ++j)
            #pragma unroll
            for (int q = 0; q < 4; ++q) acc[i][j][q] = 0.0f;

    // ---- prologue: fetch slab 0 into registers ----
    float4 avr0 = *(const float4*)(A + (size_t)(mtile + ar0) * DM + ac0);
    float4 avr1 = *(const float4*)(A + (size_t)(mtile + ar1) * DM + ac1);
    float4 bvr0 = loadB(0, bk0, bn0);
    float4 bvr1 = loadB(0, bk1, bn1);

    for (int kt = 0; kt < KITERS; ++kt) {
        // ---- store current slab registers -> smem (tf32 convert) ----
        As[ac0 + 0][ar0] = f2tf32(avr0.x);
        As[ac0 + 1][ar0] = f2tf32(avr0.y);
        As[ac0 + 2][ar0] = f2tf32(avr0.z);
        As[ac0 + 3][ar0] = f2tf32(avr0.w);
        As[ac1 + 0][ar1] = f2tf32(avr1.x);
        As[ac1 + 1][ar1] = f2tf32(avr1.y);
        As[ac1 + 2][ar1] = f2tf32(avr1.z);
        As[ac1 + 3][ar1] = f2tf32(avr1.w);
        Bs[bk0][bn0 + 0] = f2tf32(bvr0.x);
        Bs[bk0][bn0 + 1] = f2tf32(bvr0.y);
        Bs[bk0][bn0 + 2] = f2tf32(bvr0.z);
        Bs[bk0][bn0 + 3] = f2tf32(bvr0.w);
        Bs[bk1][bn1 + 0] = f2tf32(bvr1.x);
        Bs[bk1][bn1 + 1] = f2tf32(bvr1.y);
        Bs[bk1][bn1 + 2] = f2tf32(bvr1.z);
        Bs[bk1][bn1 + 3] = f2tf32(bvr1.w);
        __syncthreads();

        // ---- prefetch next slab to registers ----
        if (kt + 1 < KITERS) {
            const int k0 = (kt + 1) * BK;
            avr0 = *(const float4*)(A + (size_t)(mtile + ar0) * DM + k0 + ac0);
            avr1 = *(const float4*)(A + (size_t)(mtile + ar1) * DM + k0 + ac1);
            bvr0 = loadB(k0, bk0, bn0);
            bvr1 = loadB(k0, bk1, bn1);
        }

        // ---- compute: 2 k8-steps x (2 m16) x (8 n8) ----
        #pragma unroll
        for (int ks = 0; ks < 2; ++ks) {
            const int k8 = ks * 8;
            uint32_t af[2][4];
            #pragma unroll
            for (int im = 0; im < 2; ++im) {
                const int rb = warp_m * 32 + im * 16;
                af[im][0] = As[k8 + tg    ][rb + g    ];
                af[im][1] = As[k8 + tg    ][rb + g + 8];
                af[im][2] = As[k8 + tg + 4][rb + g    ];
                af[im][3] = As[k8 + tg + 4][rb + g + 8];
            }
            #pragma unroll
            for (int in = 0; in < 8; ++in) {
                const int cb = warp_n * 64 + in * 8;
                const uint32_t b0 = Bs[k8 + tg    ][cb + g];
                const uint32_t b1 = Bs[k8 + tg + 4][cb + g];
                #pragma unroll
                for (int im = 0; im < 2; ++im)
                    mma_tf32(acc[im][in][0], acc[im][in][1], acc[im][in][2], acc[im][in][3],
                             af[im][0], af[im][1], af[im][2], af[im][3], b0, b1);
            }
        }
        __syncthreads();
    }

    // ---- epilogue ----
    #pragma unroll
    for (int im = 0; im < 2; ++im) {
        const int r0 = mtile + warp_m * 32 + im * 16 + g;   // rows r0, r0+8
        #pragma unroll
        for (int in = 0; in < 8; ++in) {
            const int c = warp_n * 64 + in * 8 + 2 * tg;    // cols c, c+1
            if (MODE == 0) {
                const int nloc = nbase + c;
                const int h = nloc >> 6, d0 = nloc & 63;
                float* gout = (which == 0) ? g_Q : (which == 1) ? g_K : g_V;
                {
                    const int b = r0 >> 8, t = r0 & 255;
                    float2 v = make_float2(acc[im][in][0], acc[im][in][1]);
                    *(float2*)(gout + ((size_t)(b * H_ + h) * T_ + t) * DK + d0) = v;
                }
                {
                    const int r1 = r0 + 8;
                    const int b = r1 >> 8, t = r1 & 255;
                    float2 v = make_float2(acc[im][in][2], acc[im][in][3]);
                    *(float2*)(gout + ((size_t)(b * H_ + h) * T_ + t) * DK + d0) = v;
                }
            } else {
                float2 v0 = make_float2(acc[im][in][0], acc[im][in][1]);
                float2 v1 = make_float2(acc[im][in][2], acc[im][in][3]);
                *(float2*)(outp + (size_t)r0 * DM + ntile + c) = v0;
                *(float2*)(outp + (size_t)(r0 + 8) * DM + ntile + c) = v1;
            }
        }
    }
}

// ---------------------------------------------------------------------------
// Causal attention per (b,h): thread-per-query-row, online softmax,
// K/V (256x64 fp32 each) resident in 128 KB SMEM.
// ---------------------------------------------------------------------------
__global__ __launch_bounds__(256) void attn_kernel()
{
    extern __shared__ float smf[];
    float* Ks = smf;
    float* Vs = smf + T_ * DK;

    const int bid = blockIdx.x;
    const int b = bid >> 3;
    const int h = bid & 7;
    const size_t base = (size_t)(b * H_ + h) * T_ * DK;
    const int tid = threadIdx.x;

    const float4* gk = (const float4*)(g_K + base);
    const float4* gv = (const float4*)(g_V + base);
    #pragma unroll
    for (int i = tid; i < T_ * DK / 4; i += 256) {
        ((float4*)Ks)[i] = gk[i];
        ((float4*)Vs)[i] = gv[i];
    }

    float q[DK];
    {
        const float4* gq = (const float4*)(g_Q + base + (size_t)tid * DK);
        #pragma unroll
        for (int i = 0; i < DK / 4; ++i) {
            float4 v = gq[i];
            q[i * 4 + 0] = v.x; q[i * 4 + 1] = v.y;
            q[i * 4 + 2] = v.z; q[i * 4 + 3] = v.w;
        }
    }
    __syncthreads();

    const float scale = 0.04419417382415922f;   // 1/sqrt(512)

    float m = -CUDART_INF_F;
    float l = 0.0f;
    float o[DK];
    #pragma unroll
    for (int d = 0; d < DK; ++d) o[d] = 0.0f;

    for (int s = 0; s <= tid; ++s) {
        const float* kr = Ks + s * DK;
        float dot = 0.0f;
        #pragma unroll
        for (int d = 0; d < DK; ++d) dot = fmaf(q[d], kr[d], dot);
        const float xv = dot * scale;

        const float nm   = fmaxf(m, xv);
        const float corr = __expf(m - nm);
        const float p    = __expf(xv - nm);
        l = l * corr + p;
        const float* vr = Vs + s * DK;
        #pragma unroll
        for (int d = 0; d < DK; ++d)
            o[d] = fmaf(o[d], corr, p * vr[d]);
        m = nm;
    }

    const float inv = 1.0f / l;
    float* op = g_att + (size_t)(b * T_ + tid) * DM + h * DK;
    #pragma unroll
    for (int d = 0; d < DK; d += 4) {
        float4 v = make_float4(o[d] * inv, o[d + 1] * inv, o[d + 2] * inv, o[d + 3] * inv);
        *(float4*)(op + d) = v;
    }
}

// ---------------------------------------------------------------------------
extern "C" void kernel_launch(void* const* d_in, const int* in_sizes, int n_in,
                              void* d_out, int out_size)
{
    const float* x  = (const float*)d_in[0];
    const float* Wq = (const float*)d_in[1];
    const float* Wk = (const float*)d_in[2];
    const float* Wv = (const float*)d_in[3];
    const float* Wo = (const float*)d_in[4];
    float* out = (float*)d_out;

    static bool attrs_done = false;
    if (!attrs_done) {
        cudaFuncSetAttribute(attn_kernel, cudaFuncAttributeMaxDynamicSharedMemorySize,
                             2 * T_ * DK * (int)sizeof(float));
        attrs_done = true;
    }

    // 1. QKV projections: logical GEMM 16384 x 1536 x 512
    gemm_mma<0><<<dim3(NTOK / BM, (3 * DM) / BN), 256>>>(x, Wq, Wk, Wv, nullptr);

    // 2. attention
    attn_kernel<<<B_ * H_, 256, 2 * T_ * DK * (int)sizeof(float)>>>();

    // 3. output projection: 16384 x 512 x 512
    gemm_mma<1><<<dim3(NTOK / BM, DM / BN), 256>>>(nullptr, Wo, nullptr, nullptr, out);
}

// round 4
// speedup vs baseline: 2.8706x; 1.5713x over previous
#include <cuda_runtime.h>
#include <math_constants.h>
#include <cstdint>

// ---------------------------------------------------------------------------
// Problem constants
// ---------------------------------------------------------------------------
namespace {
constexpr int B_  = 64;
constexpr int T_  = 256;
constexpr int DM  = 512;   // d_model
constexpr int H_  = 8;     // heads
constexpr int DK  = 64;    // head dim
constexpr int NTOK = B_ * T_;  // 16384
}

// Scratch (device globals — no allocation allowed in kernel_launch)
__device__ float g_Q[B_ * H_ * T_ * DK];
__device__ float g_K[B_ * H_ * T_ * DK];
__device__ float g_V[B_ * H_ * T_ * DK];
__device__ float g_att[NTOK * DM];

// ---------------------------------------------------------------------------
// Helpers
// ---------------------------------------------------------------------------
__device__ __forceinline__ uint32_t f2tf32(float f) {
    uint32_t r;
    asm("cvt.rna.tf32.f32 %0, %1;" : "=r"(r) : "f"(f));
    return r;
}

__device__ __forceinline__ void mma_tf32(float& d0, float& d1, float& d2, float& d3,
                                         uint32_t a0, uint32_t a1, uint32_t a2, uint32_t a3,
                                         uint32_t b0, uint32_t b1) {
    asm volatile(
        "mma.sync.aligned.m16n8k8.row.col.f32.tf32.tf32.f32 "
        "{%0,%1,%2,%3}, {%4,%5,%6,%7}, {%8,%9}, {%0,%1,%2,%3};"
        : "+f"(d0), "+f"(d1), "+f"(d2), "+f"(d3)
        : "r"(a0), "r"(a1), "r"(a2), "r"(a3), "r"(b0), "r"(b1));
}

// ---------------------------------------------------------------------------
// tf32 mma.sync GEMM. CTA tile 128(M) x 128(N), BK=16, 8 warps (4m x 2n).
// ---------------------------------------------------------------------------
namespace {
constexpr int BM = 128, BN = 128, BK = 16;
constexpr int KITERS = DM / BK;   // 32
constexpr int APAD = 4;
}

template <int MODE>
__global__ __launch_bounds__(256, 2) void gemm_mma(
    const float* __restrict__ Ain,
    const float* __restrict__ Wq,
    const float* __restrict__ Wk,
    const float* __restrict__ Wv,
    float* __restrict__ outp)
{
    __shared__ uint32_t As[BK][BM + APAD];   // [k][m] tf32 bits
    __shared__ uint32_t Bs[BK][BN + APAD];   // [k][n] tf32 bits

    const int tid  = threadIdx.x;
    const int wid  = tid >> 5;
    const int lane = tid & 31;
    const int g    = lane >> 2;
    const int tg   = lane & 3;

    const int warp_m = wid & 3;
    const int warp_n = wid >> 2;

    const int mtile = blockIdx.x * BM;
    const int ntile = blockIdx.y * BN;

    const float* A = (MODE == 0) ? Ain : (const float*)g_att;
    const float* Bsrc;
    int which = 0, nbase = 0;
    if (MODE == 0) {
        which = ntile >> 9;
        nbase = ntile & 511;
        Bsrc = (which == 0) ? Wq : (which == 1) ? Wk : Wv;
    } else {
        Bsrc = Wq;   // Wo passed in slot 0
    }

    const int ar0 = tid >> 2,        ac0 = (tid & 3) * 4;
    const int ar1 = (tid + 256) >> 2, ac1 = ((tid + 256) & 3) * 4;
    const int bk0 = tid >> 5,        bn0 = (tid & 31) * 4;
    const int bk1 = (tid + 256) >> 5, bn1 = ((tid + 256) & 31) * 4;

    auto loadB = [&](int k0, int k, int n) -> float4 {
        if (MODE == 0) {
            const int nloc = nbase + n;
            const int h = nloc >> 6, dd = nloc & 63;
            return *(const float4*)(Bsrc + ((size_t)h * DM + k0 + k) * DK + dd);
        } else {
            return *(const float4*)(Bsrc + (size_t)(k0 + k) * DM + ntile + n);
        }
    };

    float acc[2][8][4];
    #pragma unroll
    for (int i = 0; i < 2; ++i)
        #pragma unroll
        for (int j = 0; j < 8; ++j)
            #pragma unroll
            for (int q = 0; q < 4; ++q) acc[i][j][q] = 0.0f;

    float4 avr0 = *(const float4*)(A + (size_t)(mtile + ar0) * DM + ac0);
    float4 avr1 = *(const float4*)(A + (size_t)(mtile + ar1) * DM + ac1);
    float4 bvr0 = loadB(0, bk0, bn0);
    float4 bvr1 = loadB(0, bk1, bn1);

    for (int kt = 0; kt < KITERS; ++kt) {
        As[ac0 + 0][ar0] = f2tf32(avr0.x);
        As[ac0 + 1][ar0] = f2tf32(avr0.y);
        As[ac0 + 2][ar0] = f2tf32(avr0.z);
        As[ac0 + 3][ar0] = f2tf32(avr0.w);
        As[ac1 + 0][ar1] = f2tf32(avr1.x);
        As[ac1 + 1][ar1] = f2tf32(avr1.y);
        As[ac1 + 2][ar1] = f2tf32(avr1.z);
        As[ac1 + 3][ar1] = f2tf32(avr1.w);
        Bs[bk0][bn0 + 0] = f2tf32(bvr0.x);
        Bs[bk0][bn0 + 1] = f2tf32(bvr0.y);
        Bs[bk0][bn0 + 2] = f2tf32(bvr0.z);
        Bs[bk0][bn0 + 3] = f2tf32(bvr0.w);
        Bs[bk1][bn1 + 0] = f2tf32(bvr1.x);
        Bs[bk1][bn1 + 1] = f2tf32(bvr1.y);
        Bs[bk1][bn1 + 2] = f2tf32(bvr1.z);
        Bs[bk1][bn1 + 3] = f2tf32(bvr1.w);
        __syncthreads();

        if (kt + 1 < KITERS) {
            const int k0 = (kt + 1) * BK;
            avr0 = *(const float4*)(A + (size_t)(mtile + ar0) * DM + k0 + ac0);
            avr1 = *(const float4*)(A + (size_t)(mtile + ar1) * DM + k0 + ac1);
            bvr0 = loadB(k0, bk0, bn0);
            bvr1 = loadB(k0, bk1, bn1);
        }

        #pragma unroll
        for (int ks = 0; ks < 2; ++ks) {
            const int k8 = ks * 8;
            uint32_t af[2][4];
            #pragma unroll
            for (int im = 0; im < 2; ++im) {
                const int rb = warp_m * 32 + im * 16;
                af[im][0] = As[k8 + tg    ][rb + g    ];
                af[im][1] = As[k8 + tg    ][rb + g + 8];
                af[im][2] = As[k8 + tg + 4][rb + g    ];
                af[im][3] = As[k8 + tg + 4][rb + g + 8];
            }
            #pragma unroll
            for (int in = 0; in < 8; ++in) {
                const int cb = warp_n * 64 + in * 8;
                const uint32_t b0 = Bs[k8 + tg    ][cb + g];
                const uint32_t b1 = Bs[k8 + tg + 4][cb + g];
                #pragma unroll
                for (int im = 0; im < 2; ++im)
                    mma_tf32(acc[im][in][0], acc[im][in][1], acc[im][in][2], acc[im][in][3],
                             af[im][0], af[im][1], af[im][2], af[im][3], b0, b1);
            }
        }
        __syncthreads();
    }

    #pragma unroll
    for (int im = 0; im < 2; ++im) {
        const int r0 = mtile + warp_m * 32 + im * 16 + g;
        #pragma unroll
        for (int in = 0; in < 8; ++in) {
            const int c = warp_n * 64 + in * 8 + 2 * tg;
            if (MODE == 0) {
                const int nloc = nbase + c;
                const int h = nloc >> 6, d0 = nloc & 63;
                float* gout = (which == 0) ? g_Q : (which == 1) ? g_K : g_V;
                {
                    const int b = r0 >> 8, t = r0 & 255;
                    float2 v = make_float2(acc[im][in][0], acc[im][in][1]);
                    *(float2*)(gout + ((size_t)(b * H_ + h) * T_ + t) * DK + d0) = v;
                }
                {
                    const int r1 = r0 + 8;
                    const int b = r1 >> 8, t = r1 & 255;
                    float2 v = make_float2(acc[im][in][2], acc[im][in][3]);
                    *(float2*)(gout + ((size_t)(b * H_ + h) * T_ + t) * DK + d0) = v;
                }
            } else {
                float2 v0 = make_float2(acc[im][in][0], acc[im][in][1]);
                float2 v1 = make_float2(acc[im][in][2], acc[im][in][3]);
                *(float2*)(outp + (size_t)r0 * DM + ntile + c) = v0;
                *(float2*)(outp + (size_t)(r0 + 8) * DM + ntile + c) = v1;
            }
        }
    }
}

// ---------------------------------------------------------------------------
// Flash attention with mma.sync (tf32).
// grid = B*H*2.  CTA handles (bh, 128-query-row half).  8 warps x 16 rows.
// K/V prefix (tf32 bits) resident in padded SMEM; s-blocks of 64.
// ---------------------------------------------------------------------------
namespace {
constexpr int KVP = 68;                 // padded row stride (floats) for K/V
constexpr int PP  = 68;                 // padded row stride for P scratch
constexpr int SMEM_K_OFF = 0;                       // 256*68 u32
constexpr int SMEM_V_OFF = 256 * KVP;               // 256*68 u32
constexpr int SMEM_P_OFF = 2 * 256 * KVP;           // 8 warps * 16*68 u32
constexpr int ATT_SMEM_BYTES = (2 * 256 * KVP + 8 * 16 * PP) * 4;  // 174080
}

__global__ __launch_bounds__(256, 1) void attn_kernel()
{
    extern __shared__ uint32_t smu[];
    uint32_t* Ks = smu + SMEM_K_OFF;
    uint32_t* Vs = smu + SMEM_V_OFF;

    const int bid   = blockIdx.x;
    const int bh    = bid >> 1;
    const int qbase = (bid & 1) * 128;
    const int b = bh >> 3;
    const int h = bh & 7;
    const size_t base = (size_t)bh * T_ * DK;

    const int tid  = threadIdx.x;
    const int wid  = tid >> 5;
    const int lane = tid & 31;
    const int g    = lane >> 2;
    const int tg   = lane & 3;

    uint32_t* Pw = smu + SMEM_P_OFF + wid * 16 * PP;

    // ---- load K/V prefix rows [0, qbase+128) into padded SMEM as tf32 ----
    const int rows = qbase + 128;
    const float4* gk = (const float4*)(g_K + base);
    const float4* gv = (const float4*)(g_V + base);
    for (int i = tid; i < rows * (DK / 4); i += 256) {
        const int r = i >> 4;
        const int c4 = (i & 15) * 4;
        float4 kv = gk[i];
        float4 vv = gv[i];
        uint32_t* kd = Ks + r * KVP + c4;
        uint32_t* vd = Vs + r * KVP + c4;
        kd[0] = f2tf32(kv.x); kd[1] = f2tf32(kv.y);
        kd[2] = f2tf32(kv.z); kd[3] = f2tf32(kv.w);
        vd[0] = f2tf32(vv.x); vd[1] = f2tf32(vv.y);
        vd[2] = f2tf32(vv.z); vd[3] = f2tf32(vv.w);
    }

    // ---- Q fragments (held in registers, tf32) ----
    const int rw = qbase + wid * 16;          // warp's base query row
    const int rA = rw + g;                    // rows rA, rA+8
    uint32_t qf[8][4];
    {
        const float* gq = g_Q + base;
        #pragma unroll
        for (int kk = 0; kk < 8; ++kk) {
            const int c = kk * 8 + tg;
            qf[kk][0] = f2tf32(gq[(size_t)rA * DK + c]);
            qf[kk][1] = f2tf32(gq[(size_t)(rA + 8) * DK + c]);
            qf[kk][2] = f2tf32(gq[(size_t)rA * DK + c + 4]);
            qf[kk][3] = f2tf32(gq[(size_t)(rA + 8) * DK + c + 4]);
        }
    }
    __syncthreads();

    const float scale = 0.04419417382415922f;   // 1/sqrt(512)

    // online-softmax state (rows rA, rA+8); duplicated across the quad
    float mA = -CUDART_INF_F, mB = -CUDART_INF_F;
    float lA = 0.0f, lB = 0.0f;
    float o[8][4];
    #pragma unroll
    for (int in = 0; in < 8; ++in)
        #pragma unroll
        for (int j = 0; j < 4; ++j) o[in][j] = 0.0f;

    for (int s0 = 0; s0 <= rw + 15; s0 += 64) {
        // ---- S = Q K^T for this 16x64 block ----
        float sc[8][4];
        #pragma unroll
        for (int in = 0; in < 8; ++in)
            #pragma unroll
            for (int j = 0; j < 4; ++j) sc[in][j] = 0.0f;

        #pragma unroll
        for (int kk = 0; kk < 8; ++kk) {
            const int c = kk * 8 + tg;
            #pragma unroll
            for (int in = 0; in < 8; ++in) {
                const int s = s0 + in * 8 + g;
                const uint32_t b0 = Ks[s * KVP + c];
                const uint32_t b1 = Ks[s * KVP + c + 4];
                mma_tf32(sc[in][0], sc[in][1], sc[in][2], sc[in][3],
                         qf[kk][0], qf[kk][1], qf[kk][2], qf[kk][3], b0, b1);
            }
        }

        // ---- scale + causal mask ----
        const bool need_mask = (rw - s0) < 64;
        #pragma unroll
        for (int in = 0; in < 8; ++in) {
            const int c0 = s0 + in * 8 + 2 * tg;
            if (need_mask) {
                sc[in][0] = (c0     <= rA    ) ? sc[in][0] * scale : -CUDART_INF_F;
                sc[in][1] = (c0 + 1 <= rA    ) ? sc[in][1] * scale : -CUDART_INF_F;
                sc[in][2] = (c0     <= rA + 8) ? sc[in][2] * scale : -CUDART_INF_F;
                sc[in][3] = (c0 + 1 <= rA + 8) ? sc[in][3] * scale : -CUDART_INF_F;
            } else {
                sc[in][0] *= scale; sc[in][1] *= scale;
                sc[in][2] *= scale; sc[in][3] *= scale;
            }
        }

        // ---- row max over block (thread-local then quad shuffle) ----
        float bmA = -CUDART_INF_F, bmB = -CUDART_INF_F;
        #pragma unroll
        for (int in = 0; in < 8; ++in) {
            bmA = fmaxf(bmA, fmaxf(sc[in][0], sc[in][1]));
            bmB = fmaxf(bmB, fmaxf(sc[in][2], sc[in][3]));
        }
        bmA = fmaxf(bmA, __shfl_xor_sync(0xffffffffu, bmA, 1));
        bmA = fmaxf(bmA, __shfl_xor_sync(0xffffffffu, bmA, 2));
        bmB = fmaxf(bmB, __shfl_xor_sync(0xffffffffu, bmB, 1));
        bmB = fmaxf(bmB, __shfl_xor_sync(0xffffffffu, bmB, 2));

        const float nmA = fmaxf(mA, bmA);
        const float nmB = fmaxf(mB, bmB);
        const float corrA = __expf(mA - nmA);
        const float corrB = __expf(mB - nmB);
        mA = nmA; mB = nmB;

        // ---- exponentiate, row sums, write P (tf32) to per-warp smem ----
        float bsA = 0.0f, bsB = 0.0f;
        #pragma unroll
        for (int in = 0; in < 8; ++in) {
            const float p0 = __expf(sc[in][0] - nmA);
            const float p1 = __expf(sc[in][1] - nmA);
            const float p2 = __expf(sc[in][2] - nmB);
            const float p3 = __expf(sc[in][3] - nmB);
            bsA += p0 + p1;
            bsB += p2 + p3;
            const int col = in * 8 + 2 * tg;
            uint2 wA = make_uint2(f2tf32(p0), f2tf32(p1));
            uint2 wB = make_uint2(f2tf32(p2), f2tf32(p3));
            *(uint2*)(Pw + g * PP + col)       = wA;
            *(uint2*)(Pw + (g + 8) * PP + col) = wB;
        }
        bsA += __shfl_xor_sync(0xffffffffu, bsA, 1);
        bsA += __shfl_xor_sync(0xffffffffu, bsA, 2);
        bsB += __shfl_xor_sync(0xffffffffu, bsB, 1);
        bsB += __shfl_xor_sync(0xffffffffu, bsB, 2);
        lA = lA * corrA + bsA;
        lB = lB * corrB + bsB;

        // ---- rescale O accumulators ----
        #pragma unroll
        for (int in = 0; in < 8; ++in) {
            o[in][0] *= corrA; o[in][1] *= corrA;
            o[in][2] *= corrB; o[in][3] *= corrB;
        }

        __syncwarp();

        // ---- O += P V ----
        #pragma unroll
        for (int kk = 0; kk < 8; ++kk) {
            const int pc = kk * 8 + tg;
            const uint32_t a0 = Pw[g * PP + pc];
            const uint32_t a1 = Pw[(g + 8) * PP + pc];
            const uint32_t a2 = Pw[g * PP + pc + 4];
            const uint32_t a3 = Pw[(g + 8) * PP + pc + 4];
            #pragma unroll
            for (int in = 0; in < 8; ++in) {
                const int srow0 = s0 + kk * 8 + tg;
                const uint32_t b0 = Vs[srow0 * KVP + in * 8 + g];
                const uint32_t b1 = Vs[(srow0 + 4) * KVP + in * 8 + g];
                mma_tf32(o[in][0], o[in][1], o[in][2], o[in][3],
                         a0, a1, a2, a3, b0, b1);
            }
        }
        __syncwarp();
    }

    // ---- normalize and write to concat layout ----
    const float invA = 1.0f / lA;
    const float invB = 1.0f / lB;
    float* opA = g_att + (size_t)(b * T_ + rA) * DM + h * DK;
    float* opB = g_att + (size_t)(b * T_ + rA + 8) * DM + h * DK;
    #pragma unroll
    for (int in = 0; in < 8; ++in) {
        const int c = in * 8 + 2 * tg;
        *(float2*)(opA + c) = make_float2(o[in][0] * invA, o[in][1] * invA);
        *(float2*)(opB + c) = make_float2(o[in][2] * invB, o[in][3] * invB);
    }
}

// ---------------------------------------------------------------------------
extern "C" void kernel_launch(void* const* d_in, const int* in_sizes, int n_in,
                              void* d_out, int out_size)
{
    const float* x  = (const float*)d_in[0];
    const float* Wq = (const float*)d_in[1];
    const float* Wk = (const float*)d_in[2];
    const float* Wv = (const float*)d_in[3];
    const float* Wo = (const float*)d_in[4];
    float* out = (float*)d_out;

    static bool attrs_done = false;
    if (!attrs_done) {
        cudaFuncSetAttribute(attn_kernel, cudaFuncAttributeMaxDynamicSharedMemorySize,
                             ATT_SMEM_BYTES);
        attrs_done = true;
    }

    // 1. QKV projections: logical GEMM 16384 x 1536 x 512
    gemm_mma<0><<<dim3(NTOK / BM, (3 * DM) / BN), 256>>>(x, Wq, Wk, Wv, nullptr);

    // 2. flash attention
    attn_kernel<<<B_ * H_ * 2, 256, ATT_SMEM_BYTES>>>();

    // 3. output projection: 16384 x 512 x 512
    gemm_mma<1><<<dim3(NTOK / BM, DM / BN), 256>>>(nullptr, Wo, nullptr, nullptr, out);
}

// round 5
// speedup vs baseline: 3.5063x; 1.2214x over previous
#include <cuda_runtime.h>
#include <math_constants.h>
#include <cstdint>

// ---------------------------------------------------------------------------
// Problem constants
// ---------------------------------------------------------------------------
namespace {
constexpr int B_  = 64;
constexpr int T_  = 256;
constexpr int DM  = 512;   // d_model
constexpr int H_  = 8;     // heads
constexpr int DK  = 64;    // head dim
constexpr int NTOK = B_ * T_;  // 16384
}

// Scratch (device globals — no allocation allowed in kernel_launch)
__device__ float g_Q[B_ * H_ * T_ * DK];
__device__ float g_K[B_ * H_ * T_ * DK];
__device__ float g_V[B_ * H_ * T_ * DK];
__device__ float g_att[NTOK * DM];

// ---------------------------------------------------------------------------
// Helpers
// ---------------------------------------------------------------------------
__device__ __forceinline__ uint32_t f2tf32(float f) {
    uint32_t r;
    asm("cvt.rna.tf32.f32 %0, %1;" : "=r"(r) : "f"(f));
    return r;
}

__device__ __forceinline__ void mma_tf32(float& d0, float& d1, float& d2, float& d3,
                                         uint32_t a0, uint32_t a1, uint32_t a2, uint32_t a3,
                                         uint32_t b0, uint32_t b1) {
    asm volatile(
        "mma.sync.aligned.m16n8k8.row.col.f32.tf32.tf32.f32 "
        "{%0,%1,%2,%3}, {%4,%5,%6,%7}, {%8,%9}, {%0,%1,%2,%3};"
        : "+f"(d0), "+f"(d1), "+f"(d2), "+f"(d3)
        : "r"(a0), "r"(a1), "r"(a2), "r"(a3), "r"(b0), "r"(b1));
}

// ---------------------------------------------------------------------------
// tf32 mma.sync GEMM. CTA tile 128(M) x 128(N), BK=16, 4 warps (2m x 2n),
// warp tile 64x64. Double-buffered SMEM, register prefetch of next K-slab.
//
// MODE 0: qkv — A = x [16384,512]; logical B [1536,512] from Wq/Wk/Wv;
//         output scattered to g_Q/g_K/g_V [b,h,t,d].
// MODE 1: oproj — A = g_att; B = Wo [512,512]; output = d_out.
// ---------------------------------------------------------------------------
namespace {
constexpr int BM = 128, BN = 128, BK = 16;
constexpr int KITERS = DM / BK;   // 32
constexpr int APAD = 4;
}

template <int MODE>
__global__ __launch_bounds__(128, 2) void gemm_mma(
    const float* __restrict__ Ain,
    const float* __restrict__ Wq,
    const float* __restrict__ Wk,
    const float* __restrict__ Wv,
    float* __restrict__ outp)
{
    __shared__ uint32_t As[2][BK][BM + APAD];   // [k][m] tf32 bits
    __shared__ uint32_t Bs[2][BK][BN + APAD];   // [k][n] tf32 bits

    const int tid  = threadIdx.x;
    const int wid  = tid >> 5;
    const int lane = tid & 31;
    const int g    = lane >> 2;
    const int tg   = lane & 3;

    const int warp_m = wid & 1;   // 0..1 -> 64-row slice
    const int warp_n = wid >> 1;  // 0..1 -> 64-col slice

    const int mtile = blockIdx.x * BM;
    const int ntile = blockIdx.y * BN;

    const float* A = (MODE == 0) ? Ain : (const float*)g_att;
    const float* Bsrc;
    int which = 0, nbase = 0;
    if (MODE == 0) {
        which = ntile >> 9;
        nbase = ntile & 511;
        Bsrc = (which == 0) ? Wq : (which == 1) ? Wk : Wv;
    } else {
        Bsrc = Wq;   // Wo passed in slot 0
    }

    // staging indices: 4 float4 each for A and B
    int arow[4], acol[4], bkk[4], bnn[4];
    #pragma unroll
    for (int j = 0; j < 4; ++j) {
        const int ia = j * 128 + tid;
        arow[j] = ia >> 2;  acol[j] = (ia & 3) * 4;
        bkk[j]  = ia >> 5;  bnn[j]  = (ia & 31) * 4;
    }

    auto loadB = [&](int k0, int k, int n) -> float4 {
        if (MODE == 0) {
            const int nloc = nbase + n;
            const int h = nloc >> 6, dd = nloc & 63;
            return *(const float4*)(Bsrc + ((size_t)h * DM + k0 + k) * DK + dd);
        } else {
            return *(const float4*)(Bsrc + (size_t)(k0 + k) * DM + ntile + n);
        }
    };

    float4 areg[4], breg[4];
    auto gload = [&](int k0) {
        #pragma unroll
        for (int j = 0; j < 4; ++j) {
            areg[j] = *(const float4*)(A + (size_t)(mtile + arow[j]) * DM + k0 + acol[j]);
            breg[j] = loadB(k0, bkk[j], bnn[j]);
        }
    };
    auto sstore = [&](int buf) {
        #pragma unroll
        for (int j = 0; j < 4; ++j) {
            As[buf][acol[j] + 0][arow[j]] = f2tf32(areg[j].x);
            As[buf][acol[j] + 1][arow[j]] = f2tf32(areg[j].y);
            As[buf][acol[j] + 2][arow[j]] = f2tf32(areg[j].z);
            As[buf][acol[j] + 3][arow[j]] = f2tf32(areg[j].w);
            uint4 bv = make_uint4(f2tf32(breg[j].x), f2tf32(breg[j].y),
                                  f2tf32(breg[j].z), f2tf32(breg[j].w));
            *(uint4*)&Bs[buf][bkk[j]][bnn[j]] = bv;
        }
    };

    float acc[4][8][4];
    #pragma unroll
    for (int i = 0; i < 4; ++i)
        #pragma unroll
        for (int j = 0; j < 8; ++j)
            #pragma unroll
            for (int q = 0; q < 4; ++q) acc[i][j][q] = 0.0f;

    gload(0);
    sstore(0);
    __syncthreads();

    for (int kt = 0; kt < KITERS; ++kt) {
        const int buf = kt & 1;
        if (kt + 1 < KITERS) gload((kt + 1) * BK);

        #pragma unroll
        for (int ks = 0; ks < 2; ++ks) {
            const int k8 = ks * 8;
            uint32_t af[4][4];
            #pragma unroll
            for (int im = 0; im < 4; ++im) {
                const int rb = warp_m * 64 + im * 16;
                af[im][0] = As[buf][k8 + tg    ][rb + g    ];
                af[im][1] = As[buf][k8 + tg    ][rb + g + 8];
                af[im][2] = As[buf][k8 + tg + 4][rb + g    ];
                af[im][3] = As[buf][k8 + tg + 4][rb + g + 8];
            }
            #pragma unroll
            for (int in = 0; in < 8; ++in) {
                const int cb = warp_n * 64 + in * 8;
                const uint32_t b0 = Bs[buf][k8 + tg    ][cb + g];
                const uint32_t b1 = Bs[buf][k8 + tg + 4][cb + g];
                #pragma unroll
                for (int im = 0; im < 4; ++im)
                    mma_tf32(acc[im][in][0], acc[im][in][1], acc[im][in][2], acc[im][in][3],
                             af[im][0], af[im][1], af[im][2], af[im][3], b0, b1);
            }
        }

        if (kt + 1 < KITERS) {
            sstore(buf ^ 1);
            __syncthreads();
        }
    }

    // ---- epilogue ----
    #pragma unroll
    for (int im = 0; im < 4; ++im) {
        const int r0 = mtile + warp_m * 64 + im * 16 + g;
        #pragma unroll
        for (int in = 0; in < 8; ++in) {
            const int c = warp_n * 64 + in * 8 + 2 * tg;
            if (MODE == 0) {
                const int nloc = nbase + c;
                const int h = nloc >> 6, d0 = nloc & 63;
                float* gout = (which == 0) ? g_Q : (which == 1) ? g_K : g_V;
                {
                    const int b = r0 >> 8, t = r0 & 255;
                    float2 v = make_float2(acc[im][in][0], acc[im][in][1]);
                    *(float2*)(gout + ((size_t)(b * H_ + h) * T_ + t) * DK + d0) = v;
                }
                {
                    const int r1 = r0 + 8;
                    const int b = r1 >> 8, t = r1 & 255;
                    float2 v = make_float2(acc[im][in][2], acc[im][in][3]);
                    *(float2*)(gout + ((size_t)(b * H_ + h) * T_ + t) * DK + d0) = v;
                }
            } else {
                float2 v0 = make_float2(acc[im][in][0], acc[im][in][1]);
                float2 v1 = make_float2(acc[im][in][2], acc[im][in][3]);
                *(float2*)(outp + (size_t)r0 * DM + ntile + c) = v0;
                *(float2*)(outp + (size_t)(r0 + 8) * DM + ntile + c) = v1;
            }
        }
    }
}

// ---------------------------------------------------------------------------
// Flash attention with mma.sync (tf32).
// grid = B*H*2.  CTA handles (bh, 128-query-row half).  8 warps x 16 rows.
// ---------------------------------------------------------------------------
namespace {
constexpr int KVP = 68;
constexpr int PP  = 68;
constexpr int SMEM_K_OFF = 0;
constexpr int SMEM_V_OFF = 256 * KVP;
constexpr int SMEM_P_OFF = 2 * 256 * KVP;
constexpr int ATT_SMEM_BYTES = (2 * 256 * KVP + 8 * 16 * PP) * 4;  // 174080
}

__global__ __launch_bounds__(256, 1) void attn_kernel()
{
    extern __shared__ uint32_t smu[];
    uint32_t* Ks = smu + SMEM_K_OFF;
    uint32_t* Vs = smu + SMEM_V_OFF;

    const int bid   = blockIdx.x;
    const int bh    = bid >> 1;
    const int qbase = (bid & 1) * 128;
    const int b = bh >> 3;
    const int h = bh & 7;
    const size_t base = (size_t)bh * T_ * DK;

    const int tid  = threadIdx.x;
    const int wid  = tid >> 5;
    const int lane = tid & 31;
    const int g    = lane >> 2;
    const int tg   = lane & 3;

    uint32_t* Pw = smu + SMEM_P_OFF + wid * 16 * PP;

    const int rows = qbase + 128;
    const float4* gk = (const float4*)(g_K + base);
    const float4* gv = (const float4*)(g_V + base);
    for (int i = tid; i < rows * (DK / 4); i += 256) {
        const int r = i >> 4;
        const int c4 = (i & 15) * 4;
        float4 kv = gk[i];
        float4 vv = gv[i];
        uint32_t* kd = Ks + r * KVP + c4;
        uint32_t* vd = Vs + r * KVP + c4;
        kd[0] = f2tf32(kv.x); kd[1] = f2tf32(kv.y);
        kd[2] = f2tf32(kv.z); kd[3] = f2tf32(kv.w);
        vd[0] = f2tf32(vv.x); vd[1] = f2tf32(vv.y);
        vd[2] = f2tf32(vv.z); vd[3] = f2tf32(vv.w);
    }

    const int rw = qbase + wid * 16;
    const int rA = rw + g;
    uint32_t qf[8][4];
    {
        const float* gq = g_Q + base;
        #pragma unroll
        for (int kk = 0; kk < 8; ++kk) {
            const int c = kk * 8 + tg;
            qf[kk][0] = f2tf32(gq[(size_t)rA * DK + c]);
            qf[kk][1] = f2tf32(gq[(size_t)(rA + 8) * DK + c]);
            qf[kk][2] = f2tf32(gq[(size_t)rA * DK + c + 4]);
            qf[kk][3] = f2tf32(gq[(size_t)(rA + 8) * DK + c + 4]);
        }
    }
    __syncthreads();

    const float scale = 0.04419417382415922f;   // 1/sqrt(512)

    float mA = -CUDART_INF_F, mB = -CUDART_INF_F;
    float lA = 0.0f, lB = 0.0f;
    float o[8][4];
    #pragma unroll
    for (int in = 0; in < 8; ++in)
        #pragma unroll
        for (int j = 0; j < 4; ++j) o[in][j] = 0.0f;

    for (int s0 = 0; s0 <= rw + 15; s0 += 64) {
        float sc[8][4];
        #pragma unroll
        for (int in = 0; in < 8; ++in)
            #pragma unroll
            for (int j = 0; j < 4; ++j) sc[in][j] = 0.0f;

        #pragma unroll
        for (int kk = 0; kk < 8; ++kk) {
            const int c = kk * 8 + tg;
            #pragma unroll
            for (int in = 0; in < 8; ++in) {
                const int s = s0 + in * 8 + g;
                const uint32_t b0 = Ks[s * KVP + c];
                const uint32_t b1 = Ks[s * KVP + c + 4];
                mma_tf32(sc[in][0], sc[in][1], sc[in][2], sc[in][3],
                         qf[kk][0], qf[kk][1], qf[kk][2], qf[kk][3], b0, b1);
            }
        }

        const bool need_mask = (rw - s0) < 64;
        #pragma unroll
        for (int in = 0; in < 8; ++in) {
            const int c0 = s0 + in * 8 + 2 * tg;
            if (need_mask) {
                sc[in][0] = (c0     <= rA    ) ? sc[in][0] * scale : -CUDART_INF_F;
                sc[in][1] = (c0 + 1 <= rA    ) ? sc[in][1] * scale : -CUDART_INF_F;
                sc[in][2] = (c0     <= rA + 8) ? sc[in][2] * scale : -CUDART_INF_F;
                sc[in][3] = (c0 + 1 <= rA + 8) ? sc[in][3] * scale : -CUDART_INF_F;
            } else {
                sc[in][0] *= scale; sc[in][1] *= scale;
                sc[in][2] *= scale; sc[in][3] *= scale;
            }
        }

        float bmA = -CUDART_INF_F, bmB = -CUDART_INF_F;
        #pragma unroll
        for (int in = 0; in < 8; ++in) {
            bmA = fmaxf(bmA, fmaxf(sc[in][0], sc[in][1]));
            bmB = fmaxf(bmB, fmaxf(sc[in][2], sc[in][3]));
        }
        bmA = fmaxf(bmA, __shfl_xor_sync(0xffffffffu, bmA, 1));
        bmA = fmaxf(bmA, __shfl_xor_sync(0xffffffffu, bmA, 2));
        bmB = fmaxf(bmB, __shfl_xor_sync(0xffffffffu, bmB, 1));
        bmB = fmaxf(bmB, __shfl_xor_sync(0xffffffffu, bmB, 2));

        const float nmA = fmaxf(mA, bmA);
        const float nmB = fmaxf(mB, bmB);
        const float corrA = __expf(mA - nmA);
        const float corrB = __expf(mB - nmB);
        mA = nmA; mB = nmB;

        float bsA = 0.0f, bsB = 0.0f;
        #pragma unroll
        for (int in = 0; in < 8; ++in) {
            const float p0 = __expf(sc[in][0] - nmA);
            const float p1 = __expf(sc[in][1] - nmA);
            const float p2 = __expf(sc[in][2] - nmB);
            const float p3 = __expf(sc[in][3] - nmB);
            bsA += p0 + p1;
            bsB += p2 + p3;
            const int col = in * 8 + 2 * tg;
            uint2 wA = make_uint2(f2tf32(p0), f2tf32(p1));
            uint2 wB = make_uint2(f2tf32(p2), f2tf32(p3));
            *(uint2*)(Pw + g * PP + col)       = wA;
            *(uint2*)(Pw + (g + 8) * PP + col) = wB;
        }
        bsA += __shfl_xor_sync(0xffffffffu, bsA, 1);
        bsA += __shfl_xor_sync(0xffffffffu, bsA, 2);
        bsB += __shfl_xor_sync(0xffffffffu, bsB, 1);
        bsB += __shfl_xor_sync(0xffffffffu, bsB, 2);
        lA = lA * corrA + bsA;
        lB = lB * corrB + bsB;

        #pragma unroll
        for (int in = 0; in < 8; ++in) {
            o[in][0] *= corrA; o[in][1] *= corrA;
            o[in][2] *= corrB; o[in][3] *= corrB;
        }

        __syncwarp();

        #pragma unroll
        for (int kk = 0; kk < 8; ++kk) {
            const int pc = kk * 8 + tg;
            const uint32_t a0 = Pw[g * PP + pc];
            const uint32_t a1 = Pw[(g + 8) * PP + pc];
            const uint32_t a2 = Pw[g * PP + pc + 4];
            const uint32_t a3 = Pw[(g + 8) * PP + pc + 4];
            #pragma unroll
            for (int in = 0; in < 8; ++in) {
                const int srow0 = s0 + kk * 8 + tg;
                const uint32_t b0 = Vs[srow0 * KVP + in * 8 + g];
                const uint32_t b1 = Vs[(srow0 + 4) * KVP + in * 8 + g];
                mma_tf32(o[in][0], o[in][1], o[in][2], o[in][3],
                         a0, a1, a2, a3, b0, b1);
            }
        }
        __syncwarp();
    }

    const float invA = 1.0f / lA;
    const float invB = 1.0f / lB;
    float* opA = g_att + (size_t)(b * T_ + rA) * DM + h * DK;
    float* opB = g_att + (size_t)(b * T_ + rA + 8) * DM + h * DK;
    #pragma unroll
    for (int in = 0; in < 8; ++in) {
        const int c = in * 8 + 2 * tg;
        *(float2*)(opA + c) = make_float2(o[in][0] * invA, o[in][1] * invA);
        *(float2*)(opB + c) = make_float2(o[in][2] * invB, o[in][3] * invB);
    }
}

// ---------------------------------------------------------------------------
extern "C" void kernel_launch(void* const* d_in, const int* in_sizes, int n_in,
                              void* d_out, int out_size)
{
    const float* x  = (const float*)d_in[0];
    const float* Wq = (const float*)d_in[1];
    const float* Wk = (const float*)d_in[2];
    const float* Wv = (const float*)d_in[3];
    const float* Wo = (const float*)d_in[4];
    float* out = (float*)d_out;

    static bool attrs_done = false;
    if (!attrs_done) {
        cudaFuncSetAttribute(attn_kernel, cudaFuncAttributeMaxDynamicSharedMemorySize,
                             ATT_SMEM_BYTES);
        attrs_done = true;
    }

    // 1. QKV projections: logical GEMM 16384 x 1536 x 512
    gemm_mma<0><<<dim3(NTOK / BM, (3 * DM) / BN), 128>>>(x, Wq, Wk, Wv, nullptr);

    // 2. flash attention
    attn_kernel<<<B_ * H_ * 2, 256, ATT_SMEM_BYTES>>>();

    // 3. output projection: 16384 x 512 x 512
    gemm_mma<1><<<dim3(NTOK / BM, DM / BN), 128>>>(nullptr, Wo, nullptr, nullptr, out);
}

// round 6
// speedup vs baseline: 3.7340x; 1.0650x over previous
#include <cuda_runtime.h>
#include <math_constants.h>
#include <cstdint>

// ---------------------------------------------------------------------------
// Problem constants
// ---------------------------------------------------------------------------
namespace {
constexpr int B_  = 64;
constexpr int T_  = 256;
constexpr int DM  = 512;   // d_model
constexpr int H_  = 8;     // heads
constexpr int DK  = 64;    // head dim
constexpr int NTOK = B_ * T_;  // 16384

constexpr int BM = 128, BN = 128, BK = 16;
constexpr int KITERS = DM / BK;   // 32
constexpr int ASTR = 20;          // A smem row stride (floats)  [m][k]
constexpr int BSTR = 136;         // B smem k-row stride (floats) [k][n]
constexpr int WQKV = H_ * DM * DK;   // 262144
constexpr int WO_OFF = 3 * WQKV;
}

// Scratch (device globals — no allocation allowed in kernel_launch)
__device__ float g_Q[B_ * H_ * T_ * DK];
__device__ float g_K[B_ * H_ * T_ * DK];
__device__ float g_V[B_ * H_ * T_ * DK];
__device__ float g_att[NTOK * DM];
__device__ float g_xT[NTOK * DM];              // tf32-rounded x
__device__ float g_Wt[3 * WQKV + DM * DM];     // tf32-rounded Wq|Wk|Wv|Wo

// ---------------------------------------------------------------------------
// Helpers
// ---------------------------------------------------------------------------
__device__ __forceinline__ uint32_t f2tf32(float f) {
    uint32_t r;
    asm("cvt.rna.tf32.f32 %0, %1;" : "=r"(r) : "f"(f));
    return r;
}
__device__ __forceinline__ float rnd_tf32(float f) {
    return __uint_as_float(f2tf32(f));
}

__device__ __forceinline__ uint32_t smem_u32(const void* p) {
    uint32_t a;
    asm("{ .reg .u64 t; cvta.to.shared.u64 t, %1; cvt.u32.u64 %0, t; }"
        : "=r"(a) : "l"(p));
    return a;
}

__device__ __forceinline__ void cp16(uint32_t dst, const float* src) {
    asm volatile("cp.async.cg.shared.global [%0], [%1], 16;"
                 :: "r"(dst), "l"(src) : "memory");
}
__device__ __forceinline__ void cp_commit() {
    asm volatile("cp.async.commit_group;" ::: "memory");
}
__device__ __forceinline__ void cp_wait0() {
    asm volatile("cp.async.wait_group 0;" ::: "memory");
}

__device__ __forceinline__ void mma_tf32(float& d0, float& d1, float& d2, float& d3,
                                         uint32_t a0, uint32_t a1, uint32_t a2, uint32_t a3,
                                         uint32_t b0, uint32_t b1) {
    asm volatile(
        "mma.sync.aligned.m16n8k8.row.col.f32.tf32.tf32.f32 "
        "{%0,%1,%2,%3}, {%4,%5,%6,%7}, {%8,%9}, {%0,%1,%2,%3};"
        : "+f"(d0), "+f"(d1), "+f"(d2), "+f"(d3)
        : "r"(a0), "r"(a1), "r"(a2), "r"(a3), "r"(b0), "r"(b1));
}

// ---------------------------------------------------------------------------
// Prepass: RN-convert fp32 -> tf32-rounded fp32.
// which: 0 -> g_xT, 1..3 -> g_Wt (Wq/Wk/Wv slots), 4 -> g_Wt + WO_OFF.
// ---------------------------------------------------------------------------
__global__ __launch_bounds__(256) void cvt_kernel(const float4* __restrict__ src,
                                                  int n4, int which)
{
    const int i = blockIdx.x * 256 + threadIdx.x;
    if (i >= n4) return;
    float* dbase = (which == 0) ? g_xT
                 : (which == 4) ? (g_Wt + WO_OFF)
                                : (g_Wt + (which - 1) * WQKV);
    float4 v = src[i];
    float4 w = make_float4(rnd_tf32(v.x), rnd_tf32(v.y), rnd_tf32(v.z), rnd_tf32(v.w));
    ((float4*)dbase)[i] = w;
}

// ---------------------------------------------------------------------------
// tf32 mma.sync GEMM with cp.async double buffering. No CVT, no staging regs.
// CTA tile 128x128, BK=16, 4 warps (2m x 2n), warp tile 64x64.
// A smem [m][k] stride 20 (conflict-free frags), B smem [k][n] stride 136.
// MODE 0: qkv — A = g_xT; logical B [1536,512] from g_Wt; scatter to g_Q/K/V.
// MODE 1: oproj — A = g_att (tf32-rounded); B = Wo in g_Wt; output = d_out.
// ---------------------------------------------------------------------------
template <int MODE>
__global__ __launch_bounds__(128, 2) void gemm_mma(float* __restrict__ outp)
{
    __shared__ __align__(16) float As[2][BM][ASTR];
    __shared__ __align__(16) float Bs[2][BK][BSTR];

    const int tid  = threadIdx.x;
    const int wid  = tid >> 5;
    const int lane = tid & 31;
    const int g    = lane >> 2;
    const int tg   = lane & 3;
    const int warp_m = wid & 1;
    const int warp_n = wid >> 1;

    const int mtile = blockIdx.x * BM;
    const int ntile = blockIdx.y * BN;

    const float* A = (MODE == 0) ? g_xT : g_att;
    int which = 0, nbase = 0;
    if (MODE == 0) { which = ntile >> 9; nbase = ntile & 511; }

    // per-thread cp.async chunks: 4 for A, 4 for B
    const float* asrc[4];
    uint32_t adst[4];
    const float* bsrc[4];
    uint32_t bdst[4];
    const int bk_adv = (MODE == 0) ? DK : DM;   // src advance per +1 k

    #pragma unroll
    for (int j = 0; j < 4; ++j) {
        const int ia = j * 128 + tid;
        const int ar = ia >> 2, ac = (ia & 3) * 4;
        asrc[j] = A + (size_t)(mtile + ar) * DM + ac;
        adst[j] = smem_u32(&As[0][ar][ac]);

        const int bk = ia >> 5, bn = (ia & 31) * 4;
        if (MODE == 0) {
            const int nloc = nbase + bn;
            const int h = nloc >> 6, dd = nloc & 63;
            bsrc[j] = g_Wt + (size_t)which * WQKV + (size_t)h * DM * DK + (size_t)bk * DK + dd;
        } else {
            bsrc[j] = g_Wt + WO_OFF + (size_t)bk * DM + ntile + bn;
        }
        bdst[j] = smem_u32(&Bs[0][bk][bn]);
    }

    constexpr uint32_t ABUF = BM * ASTR * 4;
    constexpr uint32_t BBUF = BK * BSTR * 4;

    auto issue = [&](int k0, int buf) {
        const uint32_t ao = buf ? ABUF : 0;
        const uint32_t bo = buf ? BBUF : 0;
        #pragma unroll
        for (int j = 0; j < 4; ++j) cp16(adst[j] + ao, asrc[j] + k0);
        #pragma unroll
        for (int j = 0; j < 4; ++j) cp16(bdst[j] + bo, bsrc[j] + (size_t)k0 * bk_adv);
        cp_commit();
    };

    float acc[4][8][4];
    #pragma unroll
    for (int i = 0; i < 4; ++i)
        #pragma unroll
        for (int j = 0; j < 8; ++j)
            #pragma unroll
            for (int q = 0; q < 4; ++q) acc[i][j][q] = 0.0f;

    issue(0, 0);

    for (int kt = 0; kt < KITERS; ++kt) {
        const int buf = kt & 1;
        cp_wait0();
        __syncthreads();
        if (kt + 1 < KITERS) issue((kt + 1) * BK, buf ^ 1);

        const float (*Ab)[ASTR] = As[buf];
        const float (*Bb)[BSTR] = Bs[buf];

        #pragma unroll
        for (int ks = 0; ks < 2; ++ks) {
            const int k8 = ks * 8;
            uint32_t af[4][4];
            #pragma unroll
            for (int im = 0; im < 4; ++im) {
                const int rb = warp_m * 64 + im * 16;
                af[im][0] = __float_as_uint(Ab[rb + g    ][k8 + tg    ]);
                af[im][1] = __float_as_uint(Ab[rb + g + 8][k8 + tg    ]);
                af[im][2] = __float_as_uint(Ab[rb + g    ][k8 + tg + 4]);
                af[im][3] = __float_as_uint(Ab[rb + g + 8][k8 + tg + 4]);
            }
            #pragma unroll
            for (int in = 0; in < 8; ++in) {
                const int cb = warp_n * 64 + in * 8;
                const uint32_t b0 = __float_as_uint(Bb[k8 + tg    ][cb + g]);
                const uint32_t b1 = __float_as_uint(Bb[k8 + tg + 4][cb + g]);
                #pragma unroll
                for (int im = 0; im < 4; ++im)
                    mma_tf32(acc[im][in][0], acc[im][in][1], acc[im][in][2], acc[im][in][3],
                             af[im][0], af[im][1], af[im][2], af[im][3], b0, b1);
            }
        }
    }

    // ---- epilogue ----
    #pragma unroll
    for (int im = 0; im < 4; ++im) {
        const int r0 = mtile + warp_m * 64 + im * 16 + g;
        #pragma unroll
        for (int in = 0; in < 8; ++in) {
            const int c = warp_n * 64 + in * 8 + 2 * tg;
            if (MODE == 0) {
                const int nloc = nbase + c;
                const int h = nloc >> 6, d0 = nloc & 63;
                float* gout = (which == 0) ? g_Q : (which == 1) ? g_K : g_V;
                {
                    const int b = r0 >> 8, t = r0 & 255;
                    float2 v = make_float2(acc[im][in][0], acc[im][in][1]);
                    *(float2*)(gout + ((size_t)(b * H_ + h) * T_ + t) * DK + d0) = v;
                }
                {
                    const int r1 = r0 + 8;
                    const int b = r1 >> 8, t = r1 & 255;
                    float2 v = make_float2(acc[im][in][2], acc[im][in][3]);
                    *(float2*)(gout + ((size_t)(b * H_ + h) * T_ + t) * DK + d0) = v;
                }
            } else {
                float2 v0 = make_float2(acc[im][in][0], acc[im][in][1]);
                float2 v1 = make_float2(acc[im][in][2], acc[im][in][3]);
                *(float2*)(outp + (size_t)r0 * DM + ntile + c) = v0;
                *(float2*)(outp + (size_t)(r0 + 8) * DM + ntile + c) = v1;
            }
        }
    }
}

// ---------------------------------------------------------------------------
// Flash attention with mma.sync (tf32).
// grid = B*H*2.  CTA handles (bh, 128-query-row half).  8 warps x 16 rows.
// Epilogue writes g_att tf32-rounded so oproj can cp.async it raw.
// ---------------------------------------------------------------------------
namespace {
constexpr int KVP = 68;
constexpr int PP  = 68;
constexpr int SMEM_K_OFF = 0;
constexpr int SMEM_V_OFF = 256 * KVP;
constexpr int SMEM_P_OFF = 2 * 256 * KVP;
constexpr int ATT_SMEM_BYTES = (2 * 256 * KVP + 8 * 16 * PP) * 4;  // 174080
}

__global__ __launch_bounds__(256, 1) void attn_kernel()
{
    extern __shared__ uint32_t smu[];
    uint32_t* Ks = smu + SMEM_K_OFF;
    uint32_t* Vs = smu + SMEM_V_OFF;

    const int bid   = blockIdx.x;
    const int bh    = bid >> 1;
    const int qbase = (bid & 1) * 128;
    const int b = bh >> 3;
    const int h = bh & 7;
    const size_t base = (size_t)bh * T_ * DK;

    const int tid  = threadIdx.x;
    const int wid  = tid >> 5;
    const int lane = tid & 31;
    const int g    = lane >> 2;
    const int tg   = lane & 3;

    uint32_t* Pw = smu + SMEM_P_OFF + wid * 16 * PP;

    const int rows = qbase + 128;
    const float4* gk = (const float4*)(g_K + base);
    const float4* gv = (const float4*)(g_V + base);
    for (int i = tid; i < rows * (DK / 4); i += 256) {
        const int r = i >> 4;
        const int c4 = (i & 15) * 4;
        float4 kv = gk[i];
        float4 vv = gv[i];
        uint32_t* kd = Ks + r * KVP + c4;
        uint32_t* vd = Vs + r * KVP + c4;
        kd[0] = f2tf32(kv.x); kd[1] = f2tf32(kv.y);
        kd[2] = f2tf32(kv.z); kd[3] = f2tf32(kv.w);
        vd[0] = f2tf32(vv.x); vd[1] = f2tf32(vv.y);
        vd[2] = f2tf32(vv.z); vd[3] = f2tf32(vv.w);
    }

    const int rw = qbase + wid * 16;
    const int rA = rw + g;
    uint32_t qf[8][4];
    {
        const float* gq = g_Q + base;
        #pragma unroll
        for (int kk = 0; kk < 8; ++kk) {
            const int c = kk * 8 + tg;
            qf[kk][0] = f2tf32(gq[(size_t)rA * DK + c]);
            qf[kk][1] = f2tf32(gq[(size_t)(rA + 8) * DK + c]);
            qf[kk][2] = f2tf32(gq[(size_t)rA * DK + c + 4]);
            qf[kk][3] = f2tf32(gq[(size_t)(rA + 8) * DK + c + 4]);
        }
    }
    __syncthreads();

    const float scale = 0.04419417382415922f;   // 1/sqrt(512)

    float mA = -CUDART_INF_F, mB = -CUDART_INF_F;
    float lA = 0.0f, lB = 0.0f;
    float o[8][4];
    #pragma unroll
    for (int in = 0; in < 8; ++in)
        #pragma unroll
        for (int j = 0; j < 4; ++j) o[in][j] = 0.0f;

    for (int s0 = 0; s0 <= rw + 15; s0 += 64) {
        float sc[8][4];
        #pragma unroll
        for (int in = 0; in < 8; ++in)
            #pragma unroll
            for (int j = 0; j < 4; ++j) sc[in][j] = 0.0f;

        #pragma unroll
        for (int kk = 0; kk < 8; ++kk) {
            const int c = kk * 8 + tg;
            #pragma unroll
            for (int in = 0; in < 8; ++in) {
                const int s = s0 + in * 8 + g;
                const uint32_t b0 = Ks[s * KVP + c];
                const uint32_t b1 = Ks[s * KVP + c + 4];
                mma_tf32(sc[in][0], sc[in][1], sc[in][2], sc[in][3],
                         qf[kk][0], qf[kk][1], qf[kk][2], qf[kk][3], b0, b1);
            }
        }

        const bool need_mask = (rw - s0) < 64;
        #pragma unroll
        for (int in = 0; in < 8; ++in) {
            const int c0 = s0 + in * 8 + 2 * tg;
            if (need_mask) {
                sc[in][0] = (c0     <= rA    ) ? sc[in][0] * scale : -CUDART_INF_F;
                sc[in][1] = (c0 + 1 <= rA    ) ? sc[in][1] * scale : -CUDART_INF_F;
                sc[in][2] = (c0     <= rA + 8) ? sc[in][2] * scale : -CUDART_INF_F;
                sc[in][3] = (c0 + 1 <= rA + 8) ? sc[in][3] * scale : -CUDART_INF_F;
            } else {
                sc[in][0] *= scale; sc[in][1] *= scale;
                sc[in][2] *= scale; sc[in][3] *= scale;
            }
        }

        float bmA = -CUDART_INF_F, bmB = -CUDART_INF_F;
        #pragma unroll
        for (int in = 0; in < 8; ++in) {
            bmA = fmaxf(bmA, fmaxf(sc[in][0], sc[in][1]));
            bmB = fmaxf(bmB, fmaxf(sc[in][2], sc[in][3]));
        }
        bmA = fmaxf(bmA, __shfl_xor_sync(0xffffffffu, bmA, 1));
        bmA = fmaxf(bmA, __shfl_xor_sync(0xffffffffu, bmA, 2));
        bmB = fmaxf(bmB, __shfl_xor_sync(0xffffffffu, bmB, 1));
        bmB = fmaxf(bmB, __shfl_xor_sync(0xffffffffu, bmB, 2));

        const float nmA = fmaxf(mA, bmA);
        const float nmB = fmaxf(mB, bmB);
        const float corrA = __expf(mA - nmA);
        const float corrB = __expf(mB - nmB);
        mA = nmA; mB = nmB;

        float bsA = 0.0f, bsB = 0.0f;
        #pragma unroll
        for (int in = 0; in < 8; ++in) {
            const float p0 = __expf(sc[in][0] - nmA);
            const float p1 = __expf(sc[in][1] - nmA);
            const float p2 = __expf(sc[in][2] - nmB);
            const float p3 = __expf(sc[in][3] - nmB);
            bsA += p0 + p1;
            bsB += p2 + p3;
            const int col = in * 8 + 2 * tg;
            uint2 wA = make_uint2(f2tf32(p0), f2tf32(p1));
            uint2 wB = make_uint2(f2tf32(p2), f2tf32(p3));
            *(uint2*)(Pw + g * PP + col)       = wA;
            *(uint2*)(Pw + (g + 8) * PP + col) = wB;
        }
        bsA += __shfl_xor_sync(0xffffffffu, bsA, 1);
        bsA += __shfl_xor_sync(0xffffffffu, bsA, 2);
        bsB += __shfl_xor_sync(0xffffffffu, bsB, 1);
        bsB += __shfl_xor_sync(0xffffffffu, bsB, 2);
        lA = lA * corrA + bsA;
        lB = lB * corrB + bsB;

        #pragma unroll
        for (int in = 0; in < 8; ++in) {
            o[in][0] *= corrA; o[in][1] *= corrA;
            o[in][2] *= corrB; o[in][3] *= corrB;
        }

        __syncwarp();

        #pragma unroll
        for (int kk = 0; kk < 8; ++kk) {
            const int pc = kk * 8 + tg;
            const uint32_t a0 = Pw[g * PP + pc];
            const uint32_t a1 = Pw[(g + 8) * PP + pc];
            const uint32_t a2 = Pw[g * PP + pc + 4];
            const uint32_t a3 = Pw[(g + 8) * PP + pc + 4];
            #pragma unroll
            for (int in = 0; in < 8; ++in) {
                const int srow0 = s0 + kk * 8 + tg;
                const uint32_t b0 = Vs[srow0 * KVP + in * 8 + g];
                const uint32_t b1 = Vs[(srow0 + 4) * KVP + in * 8 + g];
                mma_tf32(o[in][0], o[in][1], o[in][2], o[in][3],
                         a0, a1, a2, a3, b0, b1);
            }
        }
        __syncwarp();
    }

    // write tf32-rounded (bit-identical to what oproj's CVT produced before)
    const float invA = 1.0f / lA;
    const float invB = 1.0f / lB;
    float* opA = g_att + (size_t)(b * T_ + rA) * DM + h * DK;
    float* opB = g_att + (size_t)(b * T_ + rA + 8) * DM + h * DK;
    #pragma unroll
    for (int in = 0; in < 8; ++in) {
        const int c = in * 8 + 2 * tg;
        *(float2*)(opA + c) = make_float2(rnd_tf32(o[in][0] * invA), rnd_tf32(o[in][1] * invA));
        *(float2*)(opB + c) = make_float2(rnd_tf32(o[in][2] * invB), rnd_tf32(o[in][3] * invB));
    }
}

// ---------------------------------------------------------------------------
extern "C" void kernel_launch(void* const* d_in, const int* in_sizes, int n_in,
                              void* d_out, int out_size)
{
    const float* x  = (const float*)d_in[0];
    const float* Wq = (const float*)d_in[1];
    const float* Wk = (const float*)d_in[2];
    const float* Wv = (const float*)d_in[3];
    const float* Wo = (const float*)d_in[4];
    float* out = (float*)d_out;

    static bool attrs_done = false;
    if (!attrs_done) {
        cudaFuncSetAttribute(attn_kernel, cudaFuncAttributeMaxDynamicSharedMemorySize,
                             ATT_SMEM_BYTES);
        attrs_done = true;
    }

    // 0. prepass: RN-convert inputs to tf32-rounded fp32
    cvt_kernel<<<(NTOK * DM / 4) / 256, 256>>>((const float4*)x,  NTOK * DM / 4, 0);
    cvt_kernel<<<(WQKV / 4) / 256, 256>>>((const float4*)Wq, WQKV / 4, 1);
    cvt_kernel<<<(WQKV / 4) / 256, 256>>>((const float4*)Wk, WQKV / 4, 2);
    cvt_kernel<<<(WQKV / 4) / 256, 256>>>((const float4*)Wv, WQKV / 4, 3);
    cvt_kernel<<<(DM * DM / 4) / 256, 256>>>((const float4*)Wo, DM * DM / 4, 4);

    // 1. QKV projections: logical GEMM 16384 x 1536 x 512
    gemm_mma<0><<<dim3(NTOK / BM, (3 * DM) / BN), 128>>>(nullptr);

    // 2. flash attention
    attn_kernel<<<B_ * H_ * 2, 256, ATT_SMEM_BYTES>>>();

    // 3. output projection: 16384 x 512 x 512
    gemm_mma<1><<<dim3(NTOK / BM, DM / BN), 128>>>(out);
}

// round 7
// speedup vs baseline: 3.9971x; 1.0704x over previous
#include <cuda_runtime.h>
#include <math_constants.h>
#include <cstdint>

// ---------------------------------------------------------------------------
// Problem constants
// ---------------------------------------------------------------------------
namespace {
constexpr int B_  = 64;
constexpr int T_  = 256;
constexpr int DM  = 512;   // d_model
constexpr int H_  = 8;     // heads
constexpr int DK  = 64;    // head dim
constexpr int NTOK = B_ * T_;  // 16384

constexpr int BM = 128, BN = 128, BK = 16;
constexpr int KITERS = DM / BK;   // 32
constexpr int ASTR = 20;          // A smem row stride (floats)  [m][k]
constexpr int BSTR = 136;         // B smem k-row stride (floats) [k][n]
constexpr int ABUFS = BM * ASTR;  // 2560 floats per stage
constexpr int BBUFS = BK * BSTR;  // 2176 floats per stage
constexpr int GEMM_SMEM = 3 * (ABUFS + BBUFS) * 4;   // 56832 B
constexpr int WQKV = H_ * DM * DK;   // 262144
constexpr int WO_OFF = 3 * WQKV;
}

// Scratch (device globals — no allocation allowed in kernel_launch)
__device__ float g_Q[B_ * H_ * T_ * DK];
__device__ float g_K[B_ * H_ * T_ * DK];
__device__ float g_V[B_ * H_ * T_ * DK];
__device__ float g_att[NTOK * DM];
__device__ float g_xT[NTOK * DM];              // tf32-rounded x
__device__ float g_Wt[3 * WQKV + DM * DM];     // tf32-rounded Wq|Wk|Wv|Wo

// ---------------------------------------------------------------------------
// Helpers
// ---------------------------------------------------------------------------
__device__ __forceinline__ uint32_t f2tf32(float f) {
    uint32_t r;
    asm("cvt.rna.tf32.f32 %0, %1;" : "=r"(r) : "f"(f));
    return r;
}
__device__ __forceinline__ float rnd_tf32(float f) {
    return __uint_as_float(f2tf32(f));
}

__device__ __forceinline__ uint32_t smem_u32(const void* p) {
    uint32_t a;
    asm("{ .reg .u64 t; cvta.to.shared.u64 t, %1; cvt.u32.u64 %0, t; }"
        : "=r"(a) : "l"(p));
    return a;
}

__device__ __forceinline__ void cp16(uint32_t dst, const float* src) {
    asm volatile("cp.async.cg.shared.global [%0], [%1], 16;"
                 :: "r"(dst), "l"(src) : "memory");
}
__device__ __forceinline__ void cp_commit() {
    asm volatile("cp.async.commit_group;" ::: "memory");
}
__device__ __forceinline__ void cp_wait0() {
    asm volatile("cp.async.wait_group 0;" ::: "memory");
}
__device__ __forceinline__ void cp_wait1() {
    asm volatile("cp.async.wait_group 1;" ::: "memory");
}

__device__ __forceinline__ void mma_tf32(float& d0, float& d1, float& d2, float& d3,
                                         uint32_t a0, uint32_t a1, uint32_t a2, uint32_t a3,
                                         uint32_t b0, uint32_t b1) {
    asm volatile(
        "mma.sync.aligned.m16n8k8.row.col.f32.tf32.tf32.f32 "
        "{%0,%1,%2,%3}, {%4,%5,%6,%7}, {%8,%9}, {%0,%1,%2,%3};"
        : "+f"(d0), "+f"(d1), "+f"(d2), "+f"(d3)
        : "r"(a0), "r"(a1), "r"(a2), "r"(a3), "r"(b0), "r"(b1));
}

// ---------------------------------------------------------------------------
// Fused prepass: RN-convert x|Wq|Wk|Wv|Wo -> g_xT, g_Wt in ONE launch.
// ---------------------------------------------------------------------------
namespace {
constexpr int NX4 = NTOK * DM / 4;   // 2097152 float4 (x)
constexpr int NW4 = WQKV / 4;        // 65536 float4 per weight
constexpr int NTOT4 = NX4 + 4 * NW4; // 2359296
}

__global__ __launch_bounds__(256) void cvt_all(
    const float4* __restrict__ x,  const float4* __restrict__ wq,
    const float4* __restrict__ wk, const float4* __restrict__ wv,
    const float4* __restrict__ wo)
{
    const int i = blockIdx.x * 256 + threadIdx.x;
    if (i >= NTOT4) return;
    const float4* src;
    float4* dst;
    if (i < NX4) {
        src = x + i;
        dst = (float4*)g_xT + i;
    } else {
        const int j = i - NX4;
        const int region = j >> 16;      // / NW4
        const int off = j & (NW4 - 1);
        src = (region == 0 ? wq : region == 1 ? wk : region == 2 ? wv : wo) + off;
        dst = (float4*)g_Wt + j;
    }
    float4 v = *src;
    *dst = make_float4(rnd_tf32(v.x), rnd_tf32(v.y), rnd_tf32(v.z), rnd_tf32(v.w));
}

// ---------------------------------------------------------------------------
// tf32 mma.sync GEMM, 3-stage cp.async pipeline, dynamic smem.
// CTA tile 128x128, BK=16, 4 warps (2m x 2n), warp tile 64x64.
// MODE 0: qkv — A = g_xT; logical B [1536,512] from g_Wt; scatter tf32-rounded
//         results to g_Q/g_K/g_V.
// MODE 1: oproj — A = g_att (tf32-rounded); B = Wo in g_Wt; output = d_out.
// ---------------------------------------------------------------------------
template <int MODE>
__global__ __launch_bounds__(128, 2) void gemm_mma(float* __restrict__ outp)
{
    extern __shared__ float gsm[];
    float* Asm = gsm;                  // 3 stages of [BM][ASTR]
    float* Bsm = gsm + 3 * ABUFS;      // 3 stages of [BK][BSTR]

    const int tid  = threadIdx.x;
    const int wid  = tid >> 5;
    const int lane = tid & 31;
    const int g    = lane >> 2;
    const int tg   = lane & 3;
    const int warp_m = wid & 1;
    const int warp_n = wid >> 1;

    const int mtile = blockIdx.x * BM;
    const int ntile = blockIdx.y * BN;

    const float* A = (MODE == 0) ? g_xT : g_att;
    int which = 0, nbase = 0;
    if (MODE == 0) { which = ntile >> 9; nbase = ntile & 511; }

    const float* asrc[4];
    uint32_t adst[4];
    const float* bsrc[4];
    uint32_t bdst[4];
    const int bk_adv = (MODE == 0) ? DK : DM;

    #pragma unroll
    for (int j = 0; j < 4; ++j) {
        const int ia = j * 128 + tid;
        const int ar = ia >> 2, ac = (ia & 3) * 4;
        asrc[j] = A + (size_t)(mtile + ar) * DM + ac;
        adst[j] = smem_u32(&Asm[ar * ASTR + ac]);

        const int bk = ia >> 5, bn = (ia & 31) * 4;
        if (MODE == 0) {
            const int nloc = nbase + bn;
            const int h = nloc >> 6, dd = nloc & 63;
            bsrc[j] = g_Wt + (size_t)which * WQKV + (size_t)h * DM * DK + (size_t)bk * DK + dd;
        } else {
            bsrc[j] = g_Wt + WO_OFF + (size_t)bk * DM + ntile + bn;
        }
        bdst[j] = smem_u32(&Bsm[bk * BSTR + bn]);
    }

    auto issue = [&](int kt) {
        const int buf = kt % 3;
        const uint32_t ao = (uint32_t)buf * ABUFS * 4;
        const uint32_t bo = (uint32_t)buf * BBUFS * 4;
        const int k0 = kt * BK;
        #pragma unroll
        for (int j = 0; j < 4; ++j) cp16(adst[j] + ao, asrc[j] + k0);
        #pragma unroll
        for (int j = 0; j < 4; ++j) cp16(bdst[j] + bo, bsrc[j] + (size_t)k0 * bk_adv);
        cp_commit();
    };

    float acc[4][8][4];
    #pragma unroll
    for (int i = 0; i < 4; ++i)
        #pragma unroll
        for (int j = 0; j < 8; ++j)
            #pragma unroll
            for (int q = 0; q < 4; ++q) acc[i][j][q] = 0.0f;

    issue(0);
    issue(1);

    for (int kt = 0; kt < KITERS; ++kt) {
        cp_wait1();          // newest group may be pending; group(kt) is done
        __syncthreads();
        if (kt + 2 < KITERS) issue(kt + 2);
        else                 cp_commit();   // empty group keeps count aligned

        const int buf = kt % 3;
        const float* Ab = Asm + buf * ABUFS;
        const float* Bb = Bsm + buf * BBUFS;

        #pragma unroll
        for (int ks = 0; ks < 2; ++ks) {
            const int k8 = ks * 8;
            uint32_t af[4][4];
            #pragma unroll
            for (int im = 0; im < 4; ++im) {
                const int rb = warp_m * 64 + im * 16;
                af[im][0] = __float_as_uint(Ab[(rb + g    ) * ASTR + k8 + tg    ]);
                af[im][1] = __float_as_uint(Ab[(rb + g + 8) * ASTR + k8 + tg    ]);
                af[im][2] = __float_as_uint(Ab[(rb + g    ) * ASTR + k8 + tg + 4]);
                af[im][3] = __float_as_uint(Ab[(rb + g + 8) * ASTR + k8 + tg + 4]);
            }
            #pragma unroll
            for (int in = 0; in < 8; ++in) {
                const int cb = warp_n * 64 + in * 8;
                const uint32_t b0 = __float_as_uint(Bb[(k8 + tg    ) * BSTR + cb + g]);
                const uint32_t b1 = __float_as_uint(Bb[(k8 + tg + 4) * BSTR + cb + g]);
                #pragma unroll
                for (int im = 0; im < 4; ++im)
                    mma_tf32(acc[im][in][0], acc[im][in][1], acc[im][in][2], acc[im][in][3],
                             af[im][0], af[im][1], af[im][2], af[im][3], b0, b1);
            }
        }
    }

    // ---- epilogue ----
    #pragma unroll
    for (int im = 0; im < 4; ++im) {
        const int r0 = mtile + warp_m * 64 + im * 16 + g;
        #pragma unroll
        for (int in = 0; in < 8; ++in) {
            const int c = warp_n * 64 + in * 8 + 2 * tg;
            if (MODE == 0) {
                // write tf32-rounded so attention can consume raw bits
                const int nloc = nbase + c;
                const int h = nloc >> 6, d0 = nloc & 63;
                float* gout = (which == 0) ? g_Q : (which == 1) ? g_K : g_V;
                {
                    const int b = r0 >> 8, t = r0 & 255;
                    float2 v = make_float2(rnd_tf32(acc[im][in][0]), rnd_tf32(acc[im][in][1]));
                    *(float2*)(gout + ((size_t)(b * H_ + h) * T_ + t) * DK + d0) = v;
                }
                {
                    const int r1 = r0 + 8;
                    const int b = r1 >> 8, t = r1 & 255;
                    float2 v = make_float2(rnd_tf32(acc[im][in][2]), rnd_tf32(acc[im][in][3]));
                    *(float2*)(gout + ((size_t)(b * H_ + h) * T_ + t) * DK + d0) = v;
                }
            } else {
                float2 v0 = make_float2(acc[im][in][0], acc[im][in][1]);
                float2 v1 = make_float2(acc[im][in][2], acc[im][in][3]);
                *(float2*)(outp + (size_t)r0 * DM + ntile + c) = v0;
                *(float2*)(outp + (size_t)(r0 + 8) * DM + ntile + c) = v1;
            }
        }
    }
}

// ---------------------------------------------------------------------------
// Flash attention, mma.sync tf32, STREAMED K/V (cp.async, 64-row double buffer).
// grid = B*H*2.  CTA = (bh, 128-query half).  8 warps x 16 rows.
// Q/K/V are already tf32-rounded by the qkv epilogue -> zero conversions here.
// smem = 102 KB -> 2 CTAs/SM.
// ---------------------------------------------------------------------------
namespace {
constexpr int KVP  = 68;
constexpr int PP   = 68;
constexpr int KBUF = 64 * KVP;                       // floats per K (or V) stage
constexpr int AV_OFF = 2 * KBUF;                     // V region (floats)
constexpr int AP_OFF = 4 * KBUF;                     // P region (floats)
constexpr int ATT_SMEM_BYTES = (4 * KBUF + 8 * 16 * PP) * 4;  // 104448
}

__global__ __launch_bounds__(256, 2) void attn_kernel()
{
    extern __shared__ uint32_t smu[];

    const int bid   = blockIdx.x;
    const int bh    = bid >> 1;
    const int qbase = (bid & 1) * 128;
    const int b = bh >> 3;
    const int h = bh & 7;
    const size_t base = (size_t)bh * T_ * DK;

    const int tid  = threadIdx.x;
    const int wid  = tid >> 5;
    const int lane = tid & 31;
    const int g    = lane >> 2;
    const int tg   = lane & 3;

    uint32_t* Pw = smu + AP_OFF + wid * 16 * PP;

    // per-thread cp.async chunk map: 4 chunks for K + 4 for V per 64-row block
    int cr[4], cc[4];
    uint32_t kdst[4], vdst[4];
    #pragma unroll
    for (int j = 0; j < 4; ++j) {
        const int idx = j * 256 + tid;     // 1024 chunks = 64 rows x 16 quads
        cr[j] = idx >> 4;
        cc[j] = (idx & 15) * 4;
        kdst[j] = smem_u32(&smu[cr[j] * KVP + cc[j]]);
        vdst[j] = smem_u32(&smu[AV_OFF + cr[j] * KVP + cc[j]]);
    }

    auto issue = [&](int blk, int buf) {
        const uint32_t off = (uint32_t)buf * KBUF * 4;
        const float* ksrc = g_K + base + (size_t)(blk * 64) * DK;
        const float* vsrc = g_V + base + (size_t)(blk * 64) * DK;
        #pragma unroll
        for (int j = 0; j < 4; ++j) cp16(kdst[j] + off, ksrc + cr[j] * DK + cc[j]);
        #pragma unroll
        for (int j = 0; j < 4; ++j) cp16(vdst[j] + off, vsrc + cr[j] * DK + cc[j]);
        cp_commit();
    };

    const int nblk = (qbase + 128) >> 6;     // 2 or 4
    issue(0, 0);

    // ---- Q fragments: raw loads (bits are already tf32) ----
    const int rw = qbase + wid * 16;
    const int rA = rw + g;
    uint32_t qf[8][4];
    {
        const float* gq = g_Q + base;
        #pragma unroll
        for (int kk = 0; kk < 8; ++kk) {
            const int c = kk * 8 + tg;
            qf[kk][0] = __float_as_uint(gq[(size_t)rA * DK + c]);
            qf[kk][1] = __float_as_uint(gq[(size_t)(rA + 8) * DK + c]);
            qf[kk][2] = __float_as_uint(gq[(size_t)rA * DK + c + 4]);
            qf[kk][3] = __float_as_uint(gq[(size_t)(rA + 8) * DK + c + 4]);
        }
    }

    const float scale = 0.04419417382415922f;   // 1/sqrt(512)

    float mA = -CUDART_INF_F, mB = -CUDART_INF_F;
    float lA = 0.0f, lB = 0.0f;
    float o[8][4];
    #pragma unroll
    for (int in = 0; in < 8; ++in)
        #pragma unroll
        for (int j = 0; j < 4; ++j) o[in][j] = 0.0f;

    for (int blk = 0; blk < nblk; ++blk) {
        cp_wait0();
        __syncthreads();
        if (blk + 1 < nblk) issue(blk + 1, (blk + 1) & 1);

        const int s0 = blk * 64;
        if (s0 <= rw + 15) {
            const uint32_t* Kb = smu + (blk & 1) * KBUF;
            const uint32_t* Vb = smu + AV_OFF + (blk & 1) * KBUF;

            // ---- S = Q K^T (16 x 64) ----
            float sc[8][4];
            #pragma unroll
            for (int in = 0; in < 8; ++in)
                #pragma unroll
                for (int j = 0; j < 4; ++j) sc[in][j] = 0.0f;

            #pragma unroll
            for (int kk = 0; kk < 8; ++kk) {
                const int c = kk * 8 + tg;
                #pragma unroll
                for (int in = 0; in < 8; ++in) {
                    const int sl = in * 8 + g;
                    const uint32_t b0 = Kb[sl * KVP + c];
                    const uint32_t b1 = Kb[sl * KVP + c + 4];
                    mma_tf32(sc[in][0], sc[in][1], sc[in][2], sc[in][3],
                             qf[kk][0], qf[kk][1], qf[kk][2], qf[kk][3], b0, b1);
                }
            }

            // ---- scale + causal mask ----
            const bool need_mask = (rw - s0) < 64;
            #pragma unroll
            for (int in = 0; in < 8; ++in) {
                const int c0 = s0 + in * 8 + 2 * tg;
                if (need_mask) {
                    sc[in][0] = (c0     <= rA    ) ? sc[in][0] * scale : -CUDART_INF_F;
                    sc[in][1] = (c0 + 1 <= rA    ) ? sc[in][1] * scale : -CUDART_INF_F;
                    sc[in][2] = (c0     <= rA + 8) ? sc[in][2] * scale : -CUDART_INF_F;
                    sc[in][3] = (c0 + 1 <= rA + 8) ? sc[in][3] * scale : -CUDART_INF_F;
                } else {
                    sc[in][0] *= scale; sc[in][1] *= scale;
                    sc[in][2] *= scale; sc[in][3] *= scale;
                }
            }

            // ---- row max ----
            float bmA = -CUDART_INF_F, bmB = -CUDART_INF_F;
            #pragma unroll
            for (int in = 0; in < 8; ++in) {
                bmA = fmaxf(bmA, fmaxf(sc[in][0], sc[in][1]));
                bmB = fmaxf(bmB, fmaxf(sc[in][2], sc[in][3]));
            }
            bmA = fmaxf(bmA, __shfl_xor_sync(0xffffffffu, bmA, 1));
            bmA = fmaxf(bmA, __shfl_xor_sync(0xffffffffu, bmA, 2));
            bmB = fmaxf(bmB, __shfl_xor_sync(0xffffffffu, bmB, 1));
            bmB = fmaxf(bmB, __shfl_xor_sync(0xffffffffu, bmB, 2));

            const float nmA = fmaxf(mA, bmA);
            const float nmB = fmaxf(mB, bmB);
            const float corrA = __expf(mA - nmA);
            const float corrB = __expf(mB - nmB);
            mA = nmA; mB = nmB;

            // ---- exp, row sums, P -> per-warp smem (tf32) ----
            float bsA = 0.0f, bsB = 0.0f;
            #pragma unroll
            for (int in = 0; in < 8; ++in) {
                const float p0 = __expf(sc[in][0] - nmA);
                const float p1 = __expf(sc[in][1] - nmA);
                const float p2 = __expf(sc[in][2] - nmB);
                const float p3 = __expf(sc[in][3] - nmB);
                bsA += p0 + p1;
                bsB += p2 + p3;
                const int col = in * 8 + 2 * tg;
                uint2 wA = make_uint2(f2tf32(p0), f2tf32(p1));
                uint2 wB = make_uint2(f2tf32(p2), f2tf32(p3));
                *(uint2*)(Pw + g * PP + col)       = wA;
                *(uint2*)(Pw + (g + 8) * PP + col) = wB;
            }
            bsA += __shfl_xor_sync(0xffffffffu, bsA, 1);
            bsA += __shfl_xor_sync(0xffffffffu, bsA, 2);
            bsB += __shfl_xor_sync(0xffffffffu, bsB, 1);
            bsB += __shfl_xor_sync(0xffffffffu, bsB, 2);
            lA = lA * corrA + bsA;
            lB = lB * corrB + bsB;

            // ---- rescale O ----
            #pragma unroll
            for (int in = 0; in < 8; ++in) {
                o[in][0] *= corrA; o[in][1] *= corrA;
                o[in][2] *= corrB; o[in][3] *= corrB;
            }

            __syncwarp();

            // ---- O += P V ----
            #pragma unroll
            for (int kk = 0; kk < 8; ++kk) {
                const int pc = kk * 8 + tg;
                const uint32_t a0 = Pw[g * PP + pc];
                const uint32_t a1 = Pw[(g + 8) * PP + pc];
                const uint32_t a2 = Pw[g * PP + pc + 4];
                const uint32_t a3 = Pw[(g + 8) * PP + pc + 4];
                #pragma unroll
                for (int in = 0; in < 8; ++in) {
                    const int sl = kk * 8 + tg;
                    const uint32_t b0 = Vb[sl * KVP + in * 8 + g];
                    const uint32_t b1 = Vb[(sl + 4) * KVP + in * 8 + g];
                    mma_tf32(o[in][0], o[in][1], o[in][2], o[in][3],
                             a0, a1, a2, a3, b0, b1);
                }
            }
            __syncwarp();
        }
    }

    // ---- normalize, tf32-round, write concat layout ----
    const float invA = 1.0f / lA;
    const float invB = 1.0f / lB;
    float* opA = g_att + (size_t)(b * T_ + rA) * DM + h * DK;
    float* opB = g_att + (size_t)(b * T_ + rA + 8) * DM + h * DK;
    #pragma unroll
    for (int in = 0; in < 8; ++in) {
        const int c = in * 8 + 2 * tg;
        *(float2*)(opA + c) = make_float2(rnd_tf32(o[in][0] * invA), rnd_tf32(o[in][1] * invA));
        *(float2*)(opB + c) = make_float2(rnd_tf32(o[in][2] * invB), rnd_tf32(o[in][3] * invB));
    }
}

// ---------------------------------------------------------------------------
extern "C" void kernel_launch(void* const* d_in, const int* in_sizes, int n_in,
                              void* d_out, int out_size)
{
    const float* x  = (const float*)d_in[0];
    const float* Wq = (const float*)d_in[1];
    const float* Wk = (const float*)d_in[2];
    const float* Wv = (const float*)d_in[3];
    const float* Wo = (const float*)d_in[4];
    float* out = (float*)d_out;

    static bool attrs_done = false;
    if (!attrs_done) {
        cudaFuncSetAttribute(attn_kernel, cudaFuncAttributeMaxDynamicSharedMemorySize,
                             ATT_SMEM_BYTES);
        cudaFuncSetAttribute(gemm_mma<0>, cudaFuncAttributeMaxDynamicSharedMemorySize,
                             GEMM_SMEM);
        cudaFuncSetAttribute(gemm_mma<1>, cudaFuncAttributeMaxDynamicSharedMemorySize,
                             GEMM_SMEM);
        attrs_done = true;
    }

    // 0. fused prepass: RN-convert all inputs to tf32-rounded fp32 (1 launch)
    cvt_all<<<(NTOT4 + 255) / 256, 256>>>((const float4*)x, (const float4*)Wq,
                                          (const float4*)Wk, (const float4*)Wv,
                                          (const float4*)Wo);

    // 1. QKV projections: logical GEMM 16384 x 1536 x 512
    gemm_mma<0><<<dim3(NTOK / BM, (3 * DM) / BN), 128, GEMM_SMEM>>>(nullptr);

    // 2. flash attention (streamed K/V)
    attn_kernel<<<B_ * H_ * 2, 256, ATT_SMEM_BYTES>>>();

    // 3. output projection: 16384 x 512 x 512
    gemm_mma<1><<<dim3(NTOK / BM, DM / BN), 128, GEMM_SMEM>>>(out);
}

// round 8
// speedup vs baseline: 4.1430x; 1.0365x over previous
#include <cuda_runtime.h>
#include <math_constants.h>
#include <cstdint>

// ---------------------------------------------------------------------------
// Problem constants
// ---------------------------------------------------------------------------
namespace {
constexpr int B_  = 64;
constexpr int T_  = 256;
constexpr int DM  = 512;   // d_model
constexpr int H_  = 8;     // heads
constexpr int DK  = 64;    // head dim
constexpr int NTOK = B_ * T_;  // 16384

constexpr int BM = 128, BN = 128, BK = 32;
constexpr int KITERS = DM / BK;   // 16
constexpr int ASTR = 36;          // A smem row stride (floats)  [m][k]
constexpr int BSTR = 136;         // B smem k-row stride (floats) [k][n]
constexpr int ABUFS = BM * ASTR;  // 4608 floats per stage
constexpr int BBUFS = BK * BSTR;  // 4352 floats per stage
constexpr int GEMM_SMEM = 2 * (ABUFS + BBUFS) * 4;   // 71680 B
constexpr int WQKV = H_ * DM * DK;   // 262144
constexpr int WO_OFF = 3 * WQKV;
}

// Scratch (device globals — no allocation allowed in kernel_launch)
__device__ float g_Q[B_ * H_ * T_ * DK];
__device__ float g_K[B_ * H_ * T_ * DK];
__device__ float g_V[B_ * H_ * T_ * DK];
__device__ float g_att[NTOK * DM];
__device__ float g_xT[NTOK * DM];              // tf32-rounded x
__device__ float g_Wt[3 * WQKV + DM * DM];     // tf32-rounded Wq|Wk|Wv|Wo

// ---------------------------------------------------------------------------
// Helpers
// ---------------------------------------------------------------------------
__device__ __forceinline__ uint32_t f2tf32(float f) {
    uint32_t r;
    asm("cvt.rna.tf32.f32 %0, %1;" : "=r"(r) : "f"(f));
    return r;
}
__device__ __forceinline__ float rnd_tf32(float f) {
    return __uint_as_float(f2tf32(f));
}

__device__ __forceinline__ uint32_t smem_u32(const void* p) {
    uint32_t a;
    asm("{ .reg .u64 t; cvta.to.shared.u64 t, %1; cvt.u32.u64 %0, t; }"
        : "=r"(a) : "l"(p));
    return a;
}

__device__ __forceinline__ void cp16(uint32_t dst, const float* src) {
    asm volatile("cp.async.cg.shared.global [%0], [%1], 16;"
                 :: "r"(dst), "l"(src) : "memory");
}
__device__ __forceinline__ void cp_commit() {
    asm volatile("cp.async.commit_group;" ::: "memory");
}
__device__ __forceinline__ void cp_wait0() {
    asm volatile("cp.async.wait_group 0;" ::: "memory");
}
__device__ __forceinline__ void cp_wait1() {
    asm volatile("cp.async.wait_group 1;" ::: "memory");
}

__device__ __forceinline__ void mma_tf32(float& d0, float& d1, float& d2, float& d3,
                                         uint32_t a0, uint32_t a1, uint32_t a2, uint32_t a3,
                                         uint32_t b0, uint32_t b1) {
    asm volatile(
        "mma.sync.aligned.m16n8k8.row.col.f32.tf32.tf32.f32 "
        "{%0,%1,%2,%3}, {%4,%5,%6,%7}, {%8,%9}, {%0,%1,%2,%3};"
        : "+f"(d0), "+f"(d1), "+f"(d2), "+f"(d3)
        : "r"(a0), "r"(a1), "r"(a2), "r"(a3), "r"(b0), "r"(b1));
}

// ---------------------------------------------------------------------------
// Fused prepass: RN-convert x|Wq|Wk|Wv|Wo -> g_xT, g_Wt in ONE launch.
// ---------------------------------------------------------------------------
namespace {
constexpr int NX4 = NTOK * DM / 4;   // 2097152 float4 (x)
constexpr int NW4 = WQKV / 4;        // 65536 float4 per weight
constexpr int NTOT4 = NX4 + 4 * NW4; // 2359296
}

__global__ __launch_bounds__(256) void cvt_all(
    const float4* __restrict__ x,  const float4* __restrict__ wq,
    const float4* __restrict__ wk, const float4* __restrict__ wv,
    const float4* __restrict__ wo)
{
    const int i = blockIdx.x * 256 + threadIdx.x;
    if (i >= NTOT4) return;
    const float4* src;
    float4* dst;
    if (i < NX4) {
        src = x + i;
        dst = (float4*)g_xT + i;
    } else {
        const int j = i - NX4;
        const int region = j >> 16;      // / NW4
        const int off = j & (NW4 - 1);
        src = (region == 0 ? wq : region == 1 ? wk : region == 2 ? wv : wo) + off;
        dst = (float4*)g_Wt + j;
    }
    float4 v = *src;
    *dst = make_float4(rnd_tf32(v.x), rnd_tf32(v.y), rnd_tf32(v.z), rnd_tf32(v.w));
}

// ---------------------------------------------------------------------------
// tf32 mma.sync GEMM, BK=32, 2-stage cp.async pipeline, dynamic smem.
// CTA tile 128x128, 4 warps (2m x 2n), warp tile 64x64.
// Per k-iter: 4 fully-unrolled k8 phases (long straight-line region for ptxas).
// MODE 0: qkv — A = g_xT; logical B [1536,512] from g_Wt; scatter tf32-rounded
//         results to g_Q/g_K/g_V.
// MODE 1: oproj — A = g_att (tf32-rounded); B = Wo in g_Wt; output = d_out.
// ---------------------------------------------------------------------------
template <int MODE>
__global__ __launch_bounds__(128, 2) void gemm_mma(float* __restrict__ outp)
{
    extern __shared__ float gsm[];
    float* Asm = gsm;                  // 2 stages of [BM][ASTR]
    float* Bsm = gsm + 2 * ABUFS;      // 2 stages of [BK][BSTR]

    const int tid  = threadIdx.x;
    const int wid  = tid >> 5;
    const int lane = tid & 31;
    const int g    = lane >> 2;
    const int tg   = lane & 3;
    const int warp_m = wid & 1;
    const int warp_n = wid >> 1;

    const int mtile = blockIdx.x * BM;
    const int ntile = blockIdx.y * BN;

    const float* A = (MODE == 0) ? g_xT : g_att;
    int which = 0, nbase = 0;
    if (MODE == 0) { which = ntile >> 9; nbase = ntile & 511; }

    // per-thread cp.async chunks: 8 for A, 8 for B (BK=32 tile)
    const float* asrc[8];
    uint32_t adst[8];
    const float* bsrc[8];
    uint32_t bdst[8];
    const int bk_adv = (MODE == 0) ? DK : DM;

    #pragma unroll
    for (int j = 0; j < 8; ++j) {
        const int ia = j * 128 + tid;            // 0..1023
        const int ar = ia >> 3, ac = (ia & 7) * 4;
        asrc[j] = A + (size_t)(mtile + ar) * DM + ac;
        adst[j] = smem_u32(&Asm[ar * ASTR + ac]);

        const int bk = ia >> 5, bn = (ia & 31) * 4;
        if (MODE == 0) {
            const int nloc = nbase + bn;
            const int h = nloc >> 6, dd = nloc & 63;
            bsrc[j] = g_Wt + (size_t)which * WQKV + (size_t)h * DM * DK + (size_t)bk * DK + dd;
        } else {
            bsrc[j] = g_Wt + WO_OFF + (size_t)bk * DM + ntile + bn;
        }
        bdst[j] = smem_u32(&Bsm[bk * BSTR + bn]);
    }

    auto issue = [&](int kt) {
        const int buf = kt & 1;
        const uint32_t ao = (uint32_t)buf * ABUFS * 4;
        const uint32_t bo = (uint32_t)buf * BBUFS * 4;
        const int k0 = kt * BK;
        #pragma unroll
        for (int j = 0; j < 8; ++j) cp16(adst[j] + ao, asrc[j] + k0);
        #pragma unroll
        for (int j = 0; j < 8; ++j) cp16(bdst[j] + bo, bsrc[j] + (size_t)k0 * bk_adv);
        cp_commit();
    };

    float acc[4][8][4];
    #pragma unroll
    for (int i = 0; i < 4; ++i)
        #pragma unroll
        for (int j = 0; j < 8; ++j)
            #pragma unroll
            for (int q = 0; q < 4; ++q) acc[i][j][q] = 0.0f;

    issue(0);
    issue(1);

    for (int kt = 0; kt < KITERS; ++kt) {
        cp_wait1();          // group kt done; kt+1 may be pending
        __syncthreads();

        const int buf = kt & 1;
        const float* Ab = Asm + buf * ABUFS;
        const float* Bb = Bsm + buf * BBUFS;

        #pragma unroll
        for (int ks = 0; ks < 4; ++ks) {
            const int k8 = ks * 8;
            uint32_t af[4][4];
            #pragma unroll
            for (int im = 0; im < 4; ++im) {
                const int rb = warp_m * 64 + im * 16;
                af[im][0] = __float_as_uint(Ab[(rb + g    ) * ASTR + k8 + tg    ]);
                af[im][1] = __float_as_uint(Ab[(rb + g + 8) * ASTR + k8 + tg    ]);
                af[im][2] = __float_as_uint(Ab[(rb + g    ) * ASTR + k8 + tg + 4]);
                af[im][3] = __float_as_uint(Ab[(rb + g + 8) * ASTR + k8 + tg + 4]);
            }
            #pragma unroll
            for (int in = 0; in < 8; ++in) {
                const int cb = warp_n * 64 + in * 8;
                const uint32_t b0 = __float_as_uint(Bb[(k8 + tg    ) * BSTR + cb + g]);
                const uint32_t b1 = __float_as_uint(Bb[(k8 + tg + 4) * BSTR + cb + g]);
                #pragma unroll
                for (int im = 0; im < 4; ++im)
                    mma_tf32(acc[im][in][0], acc[im][in][1], acc[im][in][2], acc[im][in][3],
                             af[im][0], af[im][1], af[im][2], af[im][3], b0, b1);
            }
        }

        __syncthreads();     // all warps done with stage buf before overwrite
        if (kt + 2 < KITERS) issue(kt + 2);
        else                 cp_commit();   // empty group keeps count aligned
    }

    // ---- epilogue ----
    #pragma unroll
    for (int im = 0; im < 4; ++im) {
        const int r0 = mtile + warp_m * 64 + im * 16 + g;
        #pragma unroll
        for (int in = 0; in < 8; ++in) {
            const int c = warp_n * 64 + in * 8 + 2 * tg;
            if (MODE == 0) {
                // write tf32-rounded so attention can consume raw bits
                const int nloc = nbase + c;
                const int h = nloc >> 6, d0 = nloc & 63;
                float* gout = (which == 0) ? g_Q : (which == 1) ? g_K : g_V;
                {
                    const int b = r0 >> 8, t = r0 & 255;
                    float2 v = make_float2(rnd_tf32(acc[im][in][0]), rnd_tf32(acc[im][in][1]));
                    *(float2*)(gout + ((size_t)(b * H_ + h) * T_ + t) * DK + d0) = v;
                }
                {
                    const int r1 = r0 + 8;
                    const int b = r1 >> 8, t = r1 & 255;
                    float2 v = make_float2(rnd_tf32(acc[im][in][2]), rnd_tf32(acc[im][in][3]));
                    *(float2*)(gout + ((size_t)(b * H_ + h) * T_ + t) * DK + d0) = v;
                }
            } else {
                float2 v0 = make_float2(acc[im][in][0], acc[im][in][1]);
                float2 v1 = make_float2(acc[im][in][2], acc[im][in][3]);
                *(float2*)(outp + (size_t)r0 * DM + ntile + c) = v0;
                *(float2*)(outp + (size_t)(r0 + 8) * DM + ntile + c) = v1;
            }
        }
    }
}

// ---------------------------------------------------------------------------
// Flash attention, mma.sync tf32, STREAMED K/V (cp.async, 64-row double buffer).
// grid = B*H*2.  CTA = (bh, 128-query half).  8 warps x 16 rows.
// Q/K/V are already tf32-rounded by the qkv epilogue -> zero conversions here.
// ---------------------------------------------------------------------------
namespace {
constexpr int KVP  = 68;
constexpr int PP   = 68;
constexpr int KBUF = 64 * KVP;                       // floats per K (or V) stage
constexpr int AV_OFF = 2 * KBUF;                     // V region (floats)
constexpr int AP_OFF = 4 * KBUF;                     // P region (floats)
constexpr int ATT_SMEM_BYTES = (4 * KBUF + 8 * 16 * PP) * 4;  // 104448
}

__global__ __launch_bounds__(256, 2) void attn_kernel()
{
    extern __shared__ uint32_t smu[];

    const int bid   = blockIdx.x;
    const int bh    = bid >> 1;
    const int qbase = (bid & 1) * 128;
    const int b = bh >> 3;
    const int h = bh & 7;
    const size_t base = (size_t)bh * T_ * DK;

    const int tid  = threadIdx.x;
    const int wid  = tid >> 5;
    const int lane = tid & 31;
    const int g    = lane >> 2;
    const int tg   = lane & 3;

    uint32_t* Pw = smu + AP_OFF + wid * 16 * PP;

    // per-thread cp.async chunk map: 4 chunks for K + 4 for V per 64-row block
    int cr[4], cc[4];
    uint32_t kdst[4], vdst[4];
    #pragma unroll
    for (int j = 0; j < 4; ++j) {
        const int idx = j * 256 + tid;     // 1024 chunks = 64 rows x 16 quads
        cr[j] = idx >> 4;
        cc[j] = (idx & 15) * 4;
        kdst[j] = smem_u32(&smu[cr[j] * KVP + cc[j]]);
        vdst[j] = smem_u32(&smu[AV_OFF + cr[j] * KVP + cc[j]]);
    }

    auto issue = [&](int blk, int buf) {
        const uint32_t off = (uint32_t)buf * KBUF * 4;
        const float* ksrc = g_K + base + (size_t)(blk * 64) * DK;
        const float* vsrc = g_V + base + (size_t)(blk * 64) * DK;
        #pragma unroll
        for (int j = 0; j < 4; ++j) cp16(kdst[j] + off, ksrc + cr[j] * DK + cc[j]);
        #pragma unroll
        for (int j = 0; j < 4; ++j) cp16(vdst[j] + off, vsrc + cr[j] * DK + cc[j]);
        cp_commit();
    };

    const int nblk = (qbase + 128) >> 6;     // 2 or 4
    issue(0, 0);

    // ---- Q fragments: raw loads (bits are already tf32) ----
    const int rw = qbase + wid * 16;
    const int rA = rw + g;
    uint32_t qf[8][4];
    {
        const float* gq = g_Q + base;
        #pragma unroll
        for (int kk = 0; kk < 8; ++kk) {
            const int c = kk * 8 + tg;
            qf[kk][0] = __float_as_uint(gq[(size_t)rA * DK + c]);
            qf[kk][1] = __float_as_uint(gq[(size_t)(rA + 8) * DK + c]);
            qf[kk][2] = __float_as_uint(gq[(size_t)rA * DK + c + 4]);
            qf[kk][3] = __float_as_uint(gq[(size_t)(rA + 8) * DK + c + 4]);
        }
    }

    const float scale = 0.04419417382415922f;   // 1/sqrt(512)

    float mA = -CUDART_INF_F, mB = -CUDART_INF_F;
    float lA = 0.0f, lB = 0.0f;
    float o[8][4];
    #pragma unroll
    for (int in = 0; in < 8; ++in)
        #pragma unroll
        for (int j = 0; j < 4; ++j) o[in][j] = 0.0f;

    for (int blk = 0; blk < nblk; ++blk) {
        cp_wait0();
        __syncthreads();
        if (blk + 1 < nblk) issue(blk + 1, (blk + 1) & 1);

        const int s0 = blk * 64;
        if (s0 <= rw + 15) {
            const uint32_t* Kb = smu + (blk & 1) * KBUF;
            const uint32_t* Vb = smu + AV_OFF + (blk & 1) * KBUF;

            // ---- S = Q K^T (16 x 64) ----
            float sc[8][4];
            #pragma unroll
            for (int in = 0; in < 8; ++in)
                #pragma unroll
                for (int j = 0; j < 4; ++j) sc[in][j] = 0.0f;

            #pragma unroll
            for (int kk = 0; kk < 8; ++kk) {
                const int c = kk * 8 + tg;
                #pragma unroll
                for (int in = 0; in < 8; ++in) {
                    const int sl = in * 8 + g;
                    const uint32_t b0 = Kb[sl * KVP + c];
                    const uint32_t b1 = Kb[sl * KVP + c + 4];
                    mma_tf32(sc[in][0], sc[in][1], sc[in][2], sc[in][3],
                             qf[kk][0], qf[kk][1], qf[kk][2], qf[kk][3], b0, b1);
                }
            }

            // ---- scale + causal mask ----
            const bool need_mask = (rw - s0) < 64;
            #pragma unroll
            for (int in = 0; in < 8; ++in) {
                const int c0 = s0 + in * 8 + 2 * tg;
                if (need_mask) {
                    sc[in][0] = (c0     <= rA    ) ? sc[in][0] * scale : -CUDART_INF_F;
                    sc[in][1] = (c0 + 1 <= rA    ) ? sc[in][1] * scale : -CUDART_INF_F;
                    sc[in][2] = (c0     <= rA + 8) ? sc[in][2] * scale : -CUDART_INF_F;
                    sc[in][3] = (c0 + 1 <= rA + 8) ? sc[in][3] * scale : -CUDART_INF_F;
                } else {
                    sc[in][0] *= scale; sc[in][1] *= scale;
                    sc[in][2] *= scale; sc[in][3] *= scale;
                }
            }

            // ---- row max ----
            float bmA = -CUDART_INF_F, bmB = -CUDART_INF_F;
            #pragma unroll
            for (int in = 0; in < 8; ++in) {
                bmA = fmaxf(bmA, fmaxf(sc[in][0], sc[in][1]));
                bmB = fmaxf(bmB, fmaxf(sc[in][2], sc[in][3]));
            }
            bmA = fmaxf(bmA, __shfl_xor_sync(0xffffffffu, bmA, 1));
            bmA = fmaxf(bmA, __shfl_xor_sync(0xffffffffu, bmA, 2));
            bmB = fmaxf(bmB, __shfl_xor_sync(0xffffffffu, bmB, 1));
            bmB = fmaxf(bmB, __shfl_xor_sync(0xffffffffu, bmB, 2));

            const float nmA = fmaxf(mA, bmA);
            const float nmB = fmaxf(mB, bmB);
            const float corrA = __expf(mA - nmA);
            const float corrB = __expf(mB - nmB);
            mA = nmA; mB = nmB;

            // ---- exp, row sums, P -> per-warp smem (tf32) ----
            float bsA = 0.0f, bsB = 0.0f;
            #pragma unroll
            for (int in = 0; in < 8; ++in) {
                const float p0 = __expf(sc[in][0] - nmA);
                const float p1 = __expf(sc[in][1] - nmA);
                const float p2 = __expf(sc[in][2] - nmB);
                const float p3 = __expf(sc[in][3] - nmB);
                bsA += p0 + p1;
                bsB += p2 + p3;
                const int col = in * 8 + 2 * tg;
                uint2 wA = make_uint2(f2tf32(p0), f2tf32(p1));
                uint2 wB = make_uint2(f2tf32(p2), f2tf32(p3));
                *(uint2*)(Pw + g * PP + col)       = wA;
                *(uint2*)(Pw + (g + 8) * PP + col) = wB;
            }
            bsA += __shfl_xor_sync(0xffffffffu, bsA, 1);
            bsA += __shfl_xor_sync(0xffffffffu, bsA, 2);
            bsB += __shfl_xor_sync(0xffffffffu, bsB, 1);
            bsB += __shfl_xor_sync(0xffffffffu, bsB, 2);
            lA = lA * corrA + bsA;
            lB = lB * corrB + bsB;

            // ---- rescale O ----
            #pragma unroll
            for (int in = 0; in < 8; ++in) {
                o[in][0] *= corrA; o[in][1] *= corrA;
                o[in][2] *= corrB; o[in][3] *= corrB;
            }

            __syncwarp();

            // ---- O += P V ----
            #pragma unroll
            for (int kk = 0; kk < 8; ++kk) {
                const int pc = kk * 8 + tg;
                const uint32_t a0 = Pw[g * PP + pc];
                const uint32_t a1 = Pw[(g + 8) * PP + pc];
                const uint32_t a2 = Pw[g * PP + pc + 4];
                const uint32_t a3 = Pw[(g + 8) * PP + pc + 4];
                #pragma unroll
                for (int in = 0; in < 8; ++in) {
                    const int sl = kk * 8 + tg;
                    const uint32_t b0 = Vb[sl * KVP + in * 8 + g];
                    const uint32_t b1 = Vb[(sl + 4) * KVP + in * 8 + g];
                    mma_tf32(o[in][0], o[in][1], o[in][2], o[in][3],
                             a0, a1, a2, a3, b0, b1);
                }
            }
            __syncwarp();
        }
    }

    // ---- normalize, tf32-round, write concat layout ----
    const float invA = 1.0f / lA;
    const float invB = 1.0f / lB;
    float* opA = g_att + (size_t)(b * T_ + rA) * DM + h * DK;
    float* opB = g_att + (size_t)(b * T_ + rA + 8) * DM + h * DK;
    #pragma unroll
    for (int in = 0; in < 8; ++in) {
        const int c = in * 8 + 2 * tg;
        *(float2*)(opA + c) = make_float2(rnd_tf32(o[in][0] * invA), rnd_tf32(o[in][1] * invA));
        *(float2*)(opB + c) = make_float2(rnd_tf32(o[in][2] * invB), rnd_tf32(o[in][3] * invB));
    }
}

// ---------------------------------------------------------------------------
extern "C" void kernel_launch(void* const* d_in, const int* in_sizes, int n_in,
                              void* d_out, int out_size)
{
    const float* x  = (const float*)d_in[0];
    const float* Wq = (const float*)d_in[1];
    const float* Wk = (const float*)d_in[2];
    const float* Wv = (const float*)d_in[3];
    const float* Wo = (const float*)d_in[4];
    float* out = (float*)d_out;

    static bool attrs_done = false;
    if (!attrs_done) {
        cudaFuncSetAttribute(attn_kernel, cudaFuncAttributeMaxDynamicSharedMemorySize,
                             ATT_SMEM_BYTES);
        cudaFuncSetAttribute(gemm_mma<0>, cudaFuncAttributeMaxDynamicSharedMemorySize,
                             GEMM_SMEM);
        cudaFuncSetAttribute(gemm_mma<1>, cudaFuncAttributeMaxDynamicSharedMemorySize,
                             GEMM_SMEM);
        attrs_done = true;
    }

    // 0. fused prepass: RN-convert all inputs to tf32-rounded fp32 (1 launch)
    cvt_all<<<(NTOT4 + 255) / 256, 256>>>((const float4*)x, (const float4*)Wq,
                                          (const float4*)Wk, (const float4*)Wv,
                                          (const float4*)Wo);

    // 1. QKV projections: logical GEMM 16384 x 1536 x 512
    gemm_mma<0><<<dim3(NTOK / BM, (3 * DM) / BN), 128, GEMM_SMEM>>>(nullptr);

    // 2. flash attention (streamed K/V)
    attn_kernel<<<B_ * H_ * 2, 256, ATT_SMEM_BYTES>>>();

    // 3. output projection: 16384 x 512 x 512
    gemm_mma<1><<<dim3(NTOK / BM, DM / BN), 128, GEMM_SMEM>>>(out);
}